// round 1
// baseline (speedup 1.0000x reference)
#include <cuda_runtime.h>
#include <math.h>

#define B_   4
#define S_   2048
#define D_   1024
#define H_   16
#define HD_  64
#define M_   (B_ * S_)      // 8192
#define NQKV (3 * D_)       // 3072
#define SCALE 0.125f        // 1/sqrt(64)

// ---------------- scratch (device globals; no runtime alloc allowed) --------
__device__ float g_wqkvT[D_ * NQKV];          // [K=1024][N=3072]
__device__ float g_woT  [D_ * D_];            // [K=1024][N=1024]
__device__ float g_q    [B_ * H_ * S_ * HD_]; // [B][H][S][64], rope applied, *scale later
__device__ float g_k    [B_ * H_ * S_ * HD_];
__device__ float g_v    [B_ * H_ * S_ * HD_];
__device__ float g_attn [M_ * D_];            // [B*S][D]
__device__ float g_cos  [S_ * (HD_ / 2)];
__device__ float g_sin  [S_ * (HD_ / 2)];

// ---------------- RoPE table ------------------------------------------------
__global__ void rope_table_kernel() {
    int idx = blockIdx.x * blockDim.x + threadIdx.x;
    if (idx >= S_ * (HD_ / 2)) return;
    int s = idx >> 5;         // /32
    int i = idx & 31;
    double inv = exp(-(2.0 * (double)i / (double)HD_) * log(10000.0));
    double ang = (double)s * inv;
    g_cos[idx] = (float)cos(ang);
    g_sin[idx] = (float)sin(ang);
}

// ---------------- weight transpose: src[rows][cols] -> dst[cols][rows] ------
__global__ void transpose_w(const float* __restrict__ src, int rows, int cols, int which) {
    __shared__ float t[32][33];
    float* dst = which ? g_woT : g_wqkvT;
    int bx = blockIdx.x * 32;   // col base in src
    int by = blockIdx.y * 32;   // row base in src
    #pragma unroll
    for (int i = threadIdx.y; i < 32; i += 8) {
        t[i][threadIdx.x] = src[(by + i) * cols + bx + threadIdx.x];
    }
    __syncthreads();
    #pragma unroll
    for (int i = threadIdx.y; i < 32; i += 8) {
        int c = bx + i;                // dst row
        int r = by + threadIdx.x;      // dst col
        dst[c * rows + r] = t[threadIdx.x][i];
    }
}

// ---------------- SGEMM 128x128x8, 256 thr, 8x8 microtile -------------------
// C[m][n] = sum_k A[m][k] * Bmat[k][n];  A stride = 1024 (K), Bmat stride = N
// EPI==0: QKV epilogue (rope + head split into g_q/g_k/g_v), A = x
// EPI==1: plain epilogue into Cout, A = g_attn
template <int N, int EPI>
__global__ __launch_bounds__(256) void sgemm_k(const float* __restrict__ A,
                                               float* __restrict__ Cout) {
    const float* __restrict__ Bmat = (EPI == 0) ? g_wqkvT : g_woT;
    const float* __restrict__ Aeff = (EPI == 0) ? A : g_attn;

    __shared__ float As[8][128];
    __shared__ float Bs[8][128];

    int tid = threadIdx.x;
    int m0 = blockIdx.y * 128;
    int n0 = blockIdx.x * 128;
    int ty = tid >> 4;          // 0..15
    int tx = tid & 15;          // 0..15

    float acc[8][8];
    #pragma unroll
    for (int i = 0; i < 8; i++)
        #pragma unroll
        for (int j = 0; j < 8; j++) acc[i][j] = 0.f;

    int arow = tid >> 1;            // 0..127
    int ac4  = (tid & 1) << 2;      // 0 or 4
    int brow = tid >> 5;            // 0..7
    int bc4  = (tid & 31) << 2;     // 0..124

    const float* aptr = Aeff + (m0 + arow) * 1024 + ac4;
    const float* bptr = Bmat + brow * N + n0 + bc4;

    for (int k0 = 0; k0 < 1024; k0 += 8) {
        float4 av = *(const float4*)(aptr + k0);
        float4 bv = *(const float4*)(bptr + (size_t)k0 * N);
        As[ac4 + 0][arow] = av.x;
        As[ac4 + 1][arow] = av.y;
        As[ac4 + 2][arow] = av.z;
        As[ac4 + 3][arow] = av.w;
        *(float4*)&Bs[brow][bc4] = bv;
        __syncthreads();
        #pragma unroll
        for (int kk = 0; kk < 8; kk++) {
            float a[8], bl[8];
            *(float4*)&a[0]  = *(const float4*)&As[kk][ty * 8];
            *(float4*)&a[4]  = *(const float4*)&As[kk][ty * 8 + 4];
            *(float4*)&bl[0] = *(const float4*)&Bs[kk][tx * 8];
            *(float4*)&bl[4] = *(const float4*)&Bs[kk][tx * 8 + 4];
            #pragma unroll
            for (int i = 0; i < 8; i++)
                #pragma unroll
                for (int j = 0; j < 8; j++) acc[i][j] = fmaf(a[i], bl[j], acc[i][j]);
        }
        __syncthreads();
    }

    if (EPI == 0) {
        // qkv epilogue: n in [0,3072). part = n/1024, d = n%1024, h = d/64, e = d%64
        // rope pairs (e even, e odd) both inside the thread's 8-col microtile.
        #pragma unroll
        for (int i = 0; i < 8; i++) {
            int m = m0 + ty * 8 + i;
            int b = m >> 11;            // /2048
            int s = m & 2047;
            #pragma unroll
            for (int jp = 0; jp < 4; jp++) {
                int n = n0 + tx * 8 + jp * 2;
                float x0 = acc[i][jp * 2];
                float x1 = acc[i][jp * 2 + 1];
                int part = n >> 10;
                int d = n & 1023;
                int h = d >> 6;
                int e = d & 63;
                int base = (((b * H_ + h) * S_) + s) * HD_ + e;
                if (part == 2) {
                    g_v[base] = x0; g_v[base + 1] = x1;
                } else {
                    float c  = g_cos[s * 32 + (e >> 1)];
                    float sn = g_sin[s * 32 + (e >> 1)];
                    float r0 = x0 * c - x1 * sn;
                    float r1 = x0 * sn + x1 * c;
                    if (part == 0) { g_q[base] = r0; g_q[base + 1] = r1; }
                    else           { g_k[base] = r0; g_k[base + 1] = r1; }
                }
            }
        }
    } else {
        #pragma unroll
        for (int i = 0; i < 8; i++) {
            int m = m0 + ty * 8 + i;
            float4 o0, o1;
            o0.x = acc[i][0]; o0.y = acc[i][1]; o0.z = acc[i][2]; o0.w = acc[i][3];
            o1.x = acc[i][4]; o1.y = acc[i][5]; o1.z = acc[i][6]; o1.w = acc[i][7];
            *(float4*)(Cout + (size_t)m * N + n0 + tx * 8)     = o0;
            *(float4*)(Cout + (size_t)m * N + n0 + tx * 8 + 4) = o1;
        }
    }
}

// ---------------- flash attention: 1 thread = 1 query row -------------------
// Block = 128 threads (128 q rows); K/V tiles of 32 rows in smem.
// Online softmax is fully thread-local (no reductions).
__global__ __launch_bounds__(128) void flash_attn(const int* __restrict__ pm) {
    int qb = blockIdx.x, h = blockIdx.y, b = blockIdx.z;
    int tid = threadIdx.x;
    int qrow = qb * 128 + tid;

    const float* qptr  = g_q + (size_t)((b * H_ + h) * S_ + qrow) * HD_;
    const float* kbase = g_k + (size_t)((b * H_ + h) * S_) * HD_;
    const float* vbase = g_v + (size_t)((b * H_ + h) * S_) * HD_;

    float qv[64];
    #pragma unroll
    for (int c = 0; c < 16; c++) {
        float4 t = *(const float4*)(qptr + c * 4);
        qv[c * 4 + 0] = t.x * SCALE;
        qv[c * 4 + 1] = t.y * SCALE;
        qv[c * 4 + 2] = t.z * SCALE;
        qv[c * 4 + 3] = t.w * SCALE;
    }
    float acc[64];
    #pragma unroll
    for (int c = 0; c < 64; c++) acc[c] = 0.f;
    float mrow = -1e30f, lsum = 0.f;

    __shared__ float Ks[32 * 68];   // stride 68 floats (272B, 16B aligned)
    __shared__ float Vs[32 * 68];
    __shared__ float pms[32];

    int ktiles = qb * 4 + 4;        // covers k in [0, qb*128+128)
    for (int kt = 0; kt < ktiles; kt++) {
        int kr0 = kt * 32;
        #pragma unroll
        for (int i = 0; i < 4; i++) {
            int idx = tid + i * 128;        // 0..511 (512 float4 = 2048 floats)
            int r  = idx >> 4;
            int c4 = (idx & 15) << 2;
            *(float4*)&Ks[r * 68 + c4] = *(const float4*)(kbase + (size_t)(kr0 + r) * 64 + c4);
            *(float4*)&Vs[r * 68 + c4] = *(const float4*)(vbase + (size_t)(kr0 + r) * 64 + c4);
        }
        if (tid < 32) pms[tid] = (float)pm[b * S_ + kr0 + tid];
        __syncthreads();

        float sc[32];
        float mt = -1e30f;
        #pragma unroll
        for (int j = 0; j < 32; j++) {
            const float* kr = &Ks[j * 68];
            float s0 = 0.f, s1 = 0.f, s2 = 0.f, s3 = 0.f;
            #pragma unroll
            for (int c4 = 0; c4 < 16; c4++) {
                float4 kk = *(const float4*)(kr + c4 * 4);   // broadcast LDS.128
                s0 = fmaf(qv[c4 * 4 + 0], kk.x, s0);
                s1 = fmaf(qv[c4 * 4 + 1], kk.y, s1);
                s2 = fmaf(qv[c4 * 4 + 2], kk.z, s2);
                s3 = fmaf(qv[c4 * 4 + 3], kk.w, s3);
            }
            float sj = (s0 + s1) + (s2 + s3);
            if (kr0 + j > qrow || pms[j] == 0.f) sj = -1e30f;
            sc[j] = sj;
            mt = fmaxf(mt, sj);
        }
        float mnew  = fmaxf(mrow, mt);
        float alpha = __expf(mrow - mnew);
        lsum *= alpha;
        #pragma unroll
        for (int c = 0; c < 64; c++) acc[c] *= alpha;
        #pragma unroll
        for (int j = 0; j < 32; j++) {
            float p = __expf(sc[j] - mnew);
            lsum += p;
            const float* vr = &Vs[j * 68];
            #pragma unroll
            for (int c4 = 0; c4 < 16; c4++) {
                float4 vv = *(const float4*)(vr + c4 * 4);
                acc[c4 * 4 + 0] = fmaf(p, vv.x, acc[c4 * 4 + 0]);
                acc[c4 * 4 + 1] = fmaf(p, vv.y, acc[c4 * 4 + 1]);
                acc[c4 * 4 + 2] = fmaf(p, vv.z, acc[c4 * 4 + 2]);
                acc[c4 * 4 + 3] = fmaf(p, vv.w, acc[c4 * 4 + 3]);
            }
        }
        mrow = mnew;
        __syncthreads();
    }

    float inv = 1.f / lsum;
    float* op = g_attn + (size_t)(b * S_ + qrow) * D_ + h * 64;
    #pragma unroll
    for (int c4 = 0; c4 < 16; c4++) {
        float4 o;
        o.x = acc[c4 * 4 + 0] * inv;
        o.y = acc[c4 * 4 + 1] * inv;
        o.z = acc[c4 * 4 + 2] * inv;
        o.w = acc[c4 * 4 + 3] * inv;
        *(float4*)(op + c4 * 4) = o;
    }
}

// ---------------- launch ----------------------------------------------------
extern "C" void kernel_launch(void* const* d_in, const int* in_sizes, int n_in,
                              void* d_out, int out_size) {
    const float* x    = (const float*)d_in[0];
    const int*   pm   = (const int*)  d_in[1];
    const float* wqkv = (const float*)d_in[2];
    const float* wo   = (const float*)d_in[3];
    float* out = (float*)d_out;

    rope_table_kernel<<<(S_ * 32 + 255) / 256, 256>>>();
    transpose_w<<<dim3(D_ / 32, NQKV / 32), dim3(32, 8)>>>(wqkv, NQKV, D_, 0);
    transpose_w<<<dim3(D_ / 32, D_  / 32), dim3(32, 8)>>>(wo,   D_,   D_, 1);

    sgemm_k<NQKV, 0><<<dim3(NQKV / 128, M_ / 128), 256>>>(x, nullptr);
    flash_attn<<<dim3(S_ / 128, H_, B_), 128>>>(pm);
    sgemm_k<D_, 1><<<dim3(D_ / 128, M_ / 128), 256>>>(nullptr, out);
}

// round 7
// speedup vs baseline: 1.8664x; 1.8664x over previous
#include <cuda_runtime.h>
#include <math.h>
#include <stdint.h>

#define B_   4
#define S_   2048
#define D_   1024
#define H_   16
#define HD_  64
#define M_   (B_ * S_)      // 8192
#define NQKV (3 * D_)       // 3072
#define SCALE 0.125f        // 1/sqrt(64)

// ---------------- scratch (device globals; no runtime alloc allowed) --------
__device__ float g_wqkvT[D_ * NQKV];          // [K=1024][N=3072]
__device__ float g_woT  [D_ * D_];            // [K=1024][N=1024]
__device__ float g_q    [B_ * H_ * S_ * HD_]; // [B][H][S][64], rope applied
__device__ float g_k    [B_ * H_ * S_ * HD_];
__device__ float g_v    [B_ * H_ * S_ * HD_];
__device__ float g_attn [M_ * D_];            // [B*S][D]
__device__ float g_cos  [S_ * (HD_ / 2)];
__device__ float g_sin  [S_ * (HD_ / 2)];

// ---------------- RoPE table ------------------------------------------------
__global__ void rope_table_kernel() {
    int idx = blockIdx.x * blockDim.x + threadIdx.x;
    if (idx >= S_ * (HD_ / 2)) return;
    int s = idx >> 5;
    int i = idx & 31;
    double inv = exp(-(2.0 * (double)i / (double)HD_) * log(10000.0));
    double ang = (double)s * inv;
    g_cos[idx] = (float)cos(ang);
    g_sin[idx] = (float)sin(ang);
}

// ---------------- weight transpose: src[rows][cols] -> dst[cols][rows] ------
__global__ void transpose_w(const float* __restrict__ src, int rows, int cols, int which) {
    __shared__ float t[32][33];
    float* dst = which ? g_woT : g_wqkvT;
    int bx = blockIdx.x * 32;
    int by = blockIdx.y * 32;
    #pragma unroll
    for (int i = threadIdx.y; i < 32; i += 8) {
        t[i][threadIdx.x] = src[(by + i) * cols + bx + threadIdx.x];
    }
    __syncthreads();
    #pragma unroll
    for (int i = threadIdx.y; i < 32; i += 8) {
        int c = bx + i;
        int r = by + threadIdx.x;
        dst[c * rows + r] = t[threadIdx.x][i];
    }
}

// ---------------- 3xTF32 tensor-core GEMM -----------------------------------
// C[m][n] = sum_k A[m][k] * Bmat[k][n]  via mma.sync m16n8k8 tf32, with
// error compensation: x = hi + lo (hi = tf32(x)), x*y ~ hiA*hiB + hiA*loB + loA*hiB.
// Block tile 128x128, BK=16, 256 threads = 8 warps (2 m x 4 n), warp tile 64x32.

#define ASTRIDE 20    // floats; banks (20g + c) % 32 form a perfect permutation
#define BSTRIDE 136   // floats; 136 % 32 == 8 -> banks (8c + g) conflict-free

__device__ __forceinline__ uint32_t f2tf32(float x) {
    uint32_t r;
    asm("cvt.rna.tf32.f32 %0, %1;" : "=r"(r) : "f"(x));
    return r;
}

__device__ __forceinline__ void mma_tf32(float* d, const uint32_t* A, const uint32_t* Bv) {
    asm volatile(
        "mma.sync.aligned.m16n8k8.row.col.f32.tf32.tf32.f32 "
        "{%0,%1,%2,%3}, {%4,%5,%6,%7}, {%8,%9}, {%0,%1,%2,%3};\n"
        : "+f"(d[0]), "+f"(d[1]), "+f"(d[2]), "+f"(d[3])
        : "r"(A[0]), "r"(A[1]), "r"(A[2]), "r"(A[3]),
          "r"(Bv[0]), "r"(Bv[1]));
}

template <int N, int EPI>
__global__ __launch_bounds__(256) void mma_gemm(const float* __restrict__ A_,
                                                float* __restrict__ Cout) {
    const float* __restrict__ Bmat = (EPI == 0) ? g_wqkvT : g_woT;
    const float* __restrict__ A    = (EPI == 0) ? A_ : g_attn;

    __shared__ float As[2][128 * ASTRIDE];
    __shared__ float Bs[2][16 * BSTRIDE];

    int tid  = threadIdx.x;
    int warp = tid >> 5, lane = tid & 31;
    int g = lane >> 2, c = lane & 3;
    int wm0 = (warp >> 2) * 64;     // 0 or 64
    int wn0 = (warp & 3) * 32;      // 0,32,64,96
    int m0 = blockIdx.y * 128;
    int n0 = blockIdx.x * 128;

    float acc[4][4][4];
    #pragma unroll
    for (int mi = 0; mi < 4; mi++)
        #pragma unroll
        for (int ni = 0; ni < 4; ni++)
            #pragma unroll
            for (int r = 0; r < 4; r++) acc[mi][ni][r] = 0.f;

    int ar0 = tid >> 2;            // 0..63
    int akq = (tid & 3) << 2;      // k quad offset
    int br0 = tid >> 5;            // 0..7
    int bnq = (tid & 31) << 2;     // n quad offset

    const float* aP = A    + (size_t)(m0 + ar0) * 1024 + akq;
    const float* bP = Bmat + (size_t)br0 * N + n0 + bnq;

    // prologue: chunk 0 -> buffer 0
    {
        float4 va0 = *(const float4*)(aP);
        float4 va1 = *(const float4*)(aP + (size_t)64 * 1024);
        float4 vb0 = *(const float4*)(bP);
        float4 vb1 = *(const float4*)(bP + (size_t)8 * N);
        *(float4*)&As[0][ar0 * ASTRIDE + akq]        = va0;
        *(float4*)&As[0][(ar0 + 64) * ASTRIDE + akq] = va1;
        *(float4*)&Bs[0][br0 * BSTRIDE + bnq]        = vb0;
        *(float4*)&Bs[0][(br0 + 8) * BSTRIDE + bnq]  = vb1;
    }
    __syncthreads();

    for (int k0 = 0; k0 < 1024; k0 += 16) {
        int cur = (k0 >> 4) & 1;
        bool more = (k0 + 16) < 1024;
        float4 va0, va1, vb0, vb1;
        if (more) {
            va0 = *(const float4*)(aP + k0 + 16);
            va1 = *(const float4*)(aP + (size_t)64 * 1024 + k0 + 16);
            vb0 = *(const float4*)(bP + (size_t)(k0 + 16) * N);
            vb1 = *(const float4*)(bP + (size_t)(k0 + 24) * N);
        }

        const float* asb = As[cur];
        const float* bsb = Bs[cur];
        #pragma unroll
        for (int kk = 0; kk < 16; kk += 8) {
            uint32_t ahi[4][4], alo[4][4], bhi[4][2], blo[4][2];
            #pragma unroll
            for (int mi = 0; mi < 4; mi++) {
                int r = wm0 + mi * 16 + g;
                float f0 = asb[r * ASTRIDE + kk + c];
                float f1 = asb[(r + 8) * ASTRIDE + kk + c];
                float f2 = asb[r * ASTRIDE + kk + c + 4];
                float f3 = asb[(r + 8) * ASTRIDE + kk + c + 4];
                ahi[mi][0] = f2tf32(f0); alo[mi][0] = f2tf32(f0 - __uint_as_float(ahi[mi][0]));
                ahi[mi][1] = f2tf32(f1); alo[mi][1] = f2tf32(f1 - __uint_as_float(ahi[mi][1]));
                ahi[mi][2] = f2tf32(f2); alo[mi][2] = f2tf32(f2 - __uint_as_float(ahi[mi][2]));
                ahi[mi][3] = f2tf32(f3); alo[mi][3] = f2tf32(f3 - __uint_as_float(ahi[mi][3]));
            }
            #pragma unroll
            for (int ni = 0; ni < 4; ni++) {
                int col = wn0 + ni * 8 + g;
                float f0 = bsb[(kk + c) * BSTRIDE + col];
                float f1 = bsb[(kk + c + 4) * BSTRIDE + col];
                bhi[ni][0] = f2tf32(f0); blo[ni][0] = f2tf32(f0 - __uint_as_float(bhi[ni][0]));
                bhi[ni][1] = f2tf32(f1); blo[ni][1] = f2tf32(f1 - __uint_as_float(bhi[ni][1]));
            }
            #pragma unroll
            for (int mi = 0; mi < 4; mi++)
                #pragma unroll
                for (int ni = 0; ni < 4; ni++) {
                    mma_tf32(acc[mi][ni], ahi[mi], bhi[ni]);   // hi*hi
                    mma_tf32(acc[mi][ni], alo[mi], bhi[ni]);   // lo*hi
                    mma_tf32(acc[mi][ni], ahi[mi], blo[ni]);   // hi*lo
                }
        }

        if (more) {
            int nxt = cur ^ 1;
            *(float4*)&As[nxt][ar0 * ASTRIDE + akq]        = va0;
            *(float4*)&As[nxt][(ar0 + 64) * ASTRIDE + akq] = va1;
            *(float4*)&Bs[nxt][br0 * BSTRIDE + bnq]        = vb0;
            *(float4*)&Bs[nxt][(br0 + 8) * BSTRIDE + bnq]  = vb1;
            __syncthreads();
        }
    }

    if (EPI == 0) {
        // n pairs (2c, 2c+1) are adjacent -> exact RoPE pairs
        #pragma unroll
        for (int mi = 0; mi < 4; mi++) {
            #pragma unroll
            for (int rr = 0; rr < 2; rr++) {
                int m = m0 + wm0 + mi * 16 + g + rr * 8;
                int b = m >> 11;
                int s = m & 2047;
                #pragma unroll
                for (int ni = 0; ni < 4; ni++) {
                    int n = n0 + wn0 + ni * 8 + 2 * c;
                    float x0 = acc[mi][ni][rr * 2];
                    float x1 = acc[mi][ni][rr * 2 + 1];
                    int part = n >> 10;
                    int d = n & 1023;
                    int h = d >> 6;
                    int e = d & 63;
                    size_t base = ((size_t)(b * H_ + h) * S_ + s) * HD_ + e;
                    if (part == 2) {
                        g_v[base] = x0; g_v[base + 1] = x1;
                    } else {
                        float co = g_cos[s * 32 + (e >> 1)];
                        float sn = g_sin[s * 32 + (e >> 1)];
                        float r0 = x0 * co - x1 * sn;
                        float r1 = x0 * sn + x1 * co;
                        if (part == 0) { g_q[base] = r0; g_q[base + 1] = r1; }
                        else           { g_k[base] = r0; g_k[base + 1] = r1; }
                    }
                }
            }
        }
    } else {
        #pragma unroll
        for (int mi = 0; mi < 4; mi++) {
            #pragma unroll
            for (int rr = 0; rr < 2; rr++) {
                int m = m0 + wm0 + mi * 16 + g + rr * 8;
                #pragma unroll
                for (int ni = 0; ni < 4; ni++) {
                    int n = n0 + wn0 + ni * 8 + 2 * c;
                    float2 o;
                    o.x = acc[mi][ni][rr * 2];
                    o.y = acc[mi][ni][rr * 2 + 1];
                    *(float2*)(Cout + (size_t)m * N + n) = o;
                }
            }
        }
    }
}

// ---------------- flash attention: 1 thread = 1 query row -------------------
// Heavy (large-qb) blocks are scheduled FIRST to kill the causal tail.
__global__ __launch_bounds__(128) void flash_attn(const int* __restrict__ pm) {
    int qb = (int)gridDim.x - 1 - (int)blockIdx.x;   // reverse: heavy first
    int h = blockIdx.y, b = blockIdx.z;
    int tid = threadIdx.x;
    int qrow = qb * 128 + tid;

    const float* qptr  = g_q + (size_t)((b * H_ + h) * S_ + qrow) * HD_;
    const float* kbase = g_k + (size_t)((b * H_ + h) * S_) * HD_;
    const float* vbase = g_v + (size_t)((b * H_ + h) * S_) * HD_;

    float qv[64];
    #pragma unroll
    for (int c = 0; c < 16; c++) {
        float4 t = *(const float4*)(qptr + c * 4);
        qv[c * 4 + 0] = t.x * SCALE;
        qv[c * 4 + 1] = t.y * SCALE;
        qv[c * 4 + 2] = t.z * SCALE;
        qv[c * 4 + 3] = t.w * SCALE;
    }
    float acc[64];
    #pragma unroll
    for (int c = 0; c < 64; c++) acc[c] = 0.f;
    float mrow = -1e30f, lsum = 0.f;

    __shared__ float Ks[32 * 68];
    __shared__ float Vs[32 * 68];
    __shared__ float pms[32];

    int ktiles = qb * 4 + 4;
    for (int kt = 0; kt < ktiles; kt++) {
        int kr0 = kt * 32;
        #pragma unroll
        for (int i = 0; i < 4; i++) {
            int idx = tid + i * 128;
            int r  = idx >> 4;
            int c4 = (idx & 15) << 2;
            *(float4*)&Ks[r * 68 + c4] = *(const float4*)(kbase + (size_t)(kr0 + r) * 64 + c4);
            *(float4*)&Vs[r * 68 + c4] = *(const float4*)(vbase + (size_t)(kr0 + r) * 64 + c4);
        }
        if (tid < 32) pms[tid] = (float)pm[b * S_ + kr0 + tid];
        __syncthreads();

        float sc[32];
        float mt = -1e30f;
        #pragma unroll
        for (int j = 0; j < 32; j++) {
            const float* kr = &Ks[j * 68];
            float s0 = 0.f, s1 = 0.f, s2 = 0.f, s3 = 0.f;
            #pragma unroll
            for (int c4 = 0; c4 < 16; c4++) {
                float4 kk = *(const float4*)(kr + c4 * 4);
                s0 = fmaf(qv[c4 * 4 + 0], kk.x, s0);
                s1 = fmaf(qv[c4 * 4 + 1], kk.y, s1);
                s2 = fmaf(qv[c4 * 4 + 2], kk.z, s2);
                s3 = fmaf(qv[c4 * 4 + 3], kk.w, s3);
            }
            float sj = (s0 + s1) + (s2 + s3);
            if (kr0 + j > qrow || pms[j] == 0.f) sj = -1e30f;
            sc[j] = sj;
            mt = fmaxf(mt, sj);
        }
        float mnew  = fmaxf(mrow, mt);
        float alpha = __expf(mrow - mnew);
        lsum *= alpha;
        #pragma unroll
        for (int c = 0; c < 64; c++) acc[c] *= alpha;
        #pragma unroll
        for (int j = 0; j < 32; j++) {
            float p = __expf(sc[j] - mnew);
            lsum += p;
            const float* vr = &Vs[j * 68];
            #pragma unroll
            for (int c4 = 0; c4 < 16; c4++) {
                float4 vv = *(const float4*)(vr + c4 * 4);
                acc[c4 * 4 + 0] = fmaf(p, vv.x, acc[c4 * 4 + 0]);
                acc[c4 * 4 + 1] = fmaf(p, vv.y, acc[c4 * 4 + 1]);
                acc[c4 * 4 + 2] = fmaf(p, vv.z, acc[c4 * 4 + 2]);
                acc[c4 * 4 + 3] = fmaf(p, vv.w, acc[c4 * 4 + 3]);
            }
        }
        mrow = mnew;
        __syncthreads();
    }

    float inv = 1.f / lsum;
    float* op = g_attn + (size_t)(b * S_ + qrow) * D_ + h * 64;
    #pragma unroll
    for (int c4 = 0; c4 < 16; c4++) {
        float4 o;
        o.x = acc[c4 * 4 + 0] * inv;
        o.y = acc[c4 * 4 + 1] * inv;
        o.z = acc[c4 * 4 + 2] * inv;
        o.w = acc[c4 * 4 + 3] * inv;
        *(float4*)(op + c4 * 4) = o;
    }
}

// ---------------- launch ----------------------------------------------------
extern "C" void kernel_launch(void* const* d_in, const int* in_sizes, int n_in,
                              void* d_out, int out_size) {
    const float* x    = (const float*)d_in[0];
    const int*   pm   = (const int*)  d_in[1];
    const float* wqkv = (const float*)d_in[2];
    const float* wo   = (const float*)d_in[3];
    float* out = (float*)d_out;

    rope_table_kernel<<<(S_ * 32 + 255) / 256, 256>>>();
    transpose_w<<<dim3(D_ / 32, NQKV / 32), dim3(32, 8)>>>(wqkv, NQKV, D_, 0);
    transpose_w<<<dim3(D_ / 32, D_  / 32), dim3(32, 8)>>>(wo,   D_,   D_, 1);

    mma_gemm<NQKV, 0><<<dim3(NQKV / 128, M_ / 128), 256>>>(x, nullptr);
    flash_attn<<<dim3(S_ / 128, H_, B_), 128>>>(pm);
    mma_gemm<D_, 1><<<dim3(D_ / 128, M_ / 128), 256>>>(nullptr, out);
}

// round 9
// speedup vs baseline: 2.8297x; 1.5162x over previous
#include <cuda_runtime.h>
#include <math.h>
#include <stdint.h>

#define B_   4
#define S_   2048
#define D_   1024
#define H_   16
#define HD_  64
#define M_   (B_ * S_)      // 8192
#define NQKV (3 * D_)       // 3072
#define SCALE 0.125f        // 1/sqrt(64)

// ---------------- scratch (device globals; no runtime alloc allowed) --------
__device__ float g_wqkvT[D_ * NQKV];          // [K=1024][N=3072]
__device__ float g_woT  [D_ * D_];            // [K=1024][N=1024]
__device__ float g_q    [B_ * H_ * S_ * HD_]; // [B][H][S][64], rope applied
__device__ float g_k    [B_ * H_ * S_ * HD_];
__device__ float g_v    [B_ * H_ * S_ * HD_];
__device__ float g_attn [M_ * D_];            // [B*S][D]
__device__ float g_cos  [S_ * (HD_ / 2)];
__device__ float g_sin  [S_ * (HD_ / 2)];

// ---------------- RoPE table ------------------------------------------------
__global__ void rope_table_kernel() {
    int idx = blockIdx.x * blockDim.x + threadIdx.x;
    if (idx >= S_ * (HD_ / 2)) return;
    int s = idx >> 5;
    int i = idx & 31;
    double inv = exp(-(2.0 * (double)i / (double)HD_) * log(10000.0));
    double ang = (double)s * inv;
    g_cos[idx] = (float)cos(ang);
    g_sin[idx] = (float)sin(ang);
}

// ---------------- weight transpose: src[rows][cols] -> dst[cols][rows] ------
__global__ void transpose_w(const float* __restrict__ src, int rows, int cols, int which) {
    __shared__ float t[32][33];
    float* dst = which ? g_woT : g_wqkvT;
    int bx = blockIdx.x * 32;
    int by = blockIdx.y * 32;
    #pragma unroll
    for (int i = threadIdx.y; i < 32; i += 8) {
        t[i][threadIdx.x] = src[(by + i) * cols + bx + threadIdx.x];
    }
    __syncthreads();
    #pragma unroll
    for (int i = threadIdx.y; i < 32; i += 8) {
        int c = bx + i;
        int r = by + threadIdx.x;
        dst[c * rows + r] = t[threadIdx.x][i];
    }
}

// ---------------- tf32 helpers ----------------------------------------------
__device__ __forceinline__ uint32_t f2tf32(float x) {
    uint32_t r;
    asm("cvt.rna.tf32.f32 %0, %1;" : "=r"(r) : "f"(x));
    return r;
}

__device__ __forceinline__ void mma_tf32(float* d, const uint32_t* A, const uint32_t* Bv) {
    asm volatile(
        "mma.sync.aligned.m16n8k8.row.col.f32.tf32.tf32.f32 "
        "{%0,%1,%2,%3}, {%4,%5,%6,%7}, {%8,%9}, {%0,%1,%2,%3};\n"
        : "+f"(d[0]), "+f"(d[1]), "+f"(d[2]), "+f"(d[3])
        : "r"(A[0]), "r"(A[1]), "r"(A[2]), "r"(A[3]),
          "r"(Bv[0]), "r"(Bv[1]));
}

// ---------------- 3xTF32 tensor-core GEMM -----------------------------------
#define ASTRIDE 20
#define BSTRIDE 136

template <int N, int EPI>
__global__ __launch_bounds__(256) void mma_gemm(const float* __restrict__ A_,
                                                float* __restrict__ Cout) {
    const float* __restrict__ Bmat = (EPI == 0) ? g_wqkvT : g_woT;
    const float* __restrict__ A    = (EPI == 0) ? A_ : g_attn;

    __shared__ float As[2][128 * ASTRIDE];
    __shared__ float Bs[2][16 * BSTRIDE];

    int tid  = threadIdx.x;
    int warp = tid >> 5, lane = tid & 31;
    int g = lane >> 2, c = lane & 3;
    int wm0 = (warp >> 2) * 64;
    int wn0 = (warp & 3) * 32;
    int m0 = blockIdx.y * 128;
    int n0 = blockIdx.x * 128;

    float acc[4][4][4];
    #pragma unroll
    for (int mi = 0; mi < 4; mi++)
        #pragma unroll
        for (int ni = 0; ni < 4; ni++)
            #pragma unroll
            for (int r = 0; r < 4; r++) acc[mi][ni][r] = 0.f;

    int ar0 = tid >> 2;
    int akq = (tid & 3) << 2;
    int br0 = tid >> 5;
    int bnq = (tid & 31) << 2;

    const float* aP = A    + (size_t)(m0 + ar0) * 1024 + akq;
    const float* bP = Bmat + (size_t)br0 * N + n0 + bnq;

    {
        float4 va0 = *(const float4*)(aP);
        float4 va1 = *(const float4*)(aP + (size_t)64 * 1024);
        float4 vb0 = *(const float4*)(bP);
        float4 vb1 = *(const float4*)(bP + (size_t)8 * N);
        *(float4*)&As[0][ar0 * ASTRIDE + akq]        = va0;
        *(float4*)&As[0][(ar0 + 64) * ASTRIDE + akq] = va1;
        *(float4*)&Bs[0][br0 * BSTRIDE + bnq]        = vb0;
        *(float4*)&Bs[0][(br0 + 8) * BSTRIDE + bnq]  = vb1;
    }
    __syncthreads();

    for (int k0 = 0; k0 < 1024; k0 += 16) {
        int cur = (k0 >> 4) & 1;
        bool more = (k0 + 16) < 1024;
        float4 va0, va1, vb0, vb1;
        if (more) {
            va0 = *(const float4*)(aP + k0 + 16);
            va1 = *(const float4*)(aP + (size_t)64 * 1024 + k0 + 16);
            vb0 = *(const float4*)(bP + (size_t)(k0 + 16) * N);
            vb1 = *(const float4*)(bP + (size_t)(k0 + 24) * N);
        }

        const float* asb = As[cur];
        const float* bsb = Bs[cur];
        #pragma unroll
        for (int kk = 0; kk < 16; kk += 8) {
            uint32_t ahi[4][4], alo[4][4], bhi[4][2], blo[4][2];
            #pragma unroll
            for (int mi = 0; mi < 4; mi++) {
                int r = wm0 + mi * 16 + g;
                float f0 = asb[r * ASTRIDE + kk + c];
                float f1 = asb[(r + 8) * ASTRIDE + kk + c];
                float f2 = asb[r * ASTRIDE + kk + c + 4];
                float f3 = asb[(r + 8) * ASTRIDE + kk + c + 4];
                ahi[mi][0] = f2tf32(f0); alo[mi][0] = f2tf32(f0 - __uint_as_float(ahi[mi][0]));
                ahi[mi][1] = f2tf32(f1); alo[mi][1] = f2tf32(f1 - __uint_as_float(ahi[mi][1]));
                ahi[mi][2] = f2tf32(f2); alo[mi][2] = f2tf32(f2 - __uint_as_float(ahi[mi][2]));
                ahi[mi][3] = f2tf32(f3); alo[mi][3] = f2tf32(f3 - __uint_as_float(ahi[mi][3]));
            }
            #pragma unroll
            for (int ni = 0; ni < 4; ni++) {
                int col = wn0 + ni * 8 + g;
                float f0 = bsb[(kk + c) * BSTRIDE + col];
                float f1 = bsb[(kk + c + 4) * BSTRIDE + col];
                bhi[ni][0] = f2tf32(f0); blo[ni][0] = f2tf32(f0 - __uint_as_float(bhi[ni][0]));
                bhi[ni][1] = f2tf32(f1); blo[ni][1] = f2tf32(f1 - __uint_as_float(bhi[ni][1]));
            }
            #pragma unroll
            for (int mi = 0; mi < 4; mi++)
                #pragma unroll
                for (int ni = 0; ni < 4; ni++) {
                    mma_tf32(acc[mi][ni], ahi[mi], bhi[ni]);
                    mma_tf32(acc[mi][ni], alo[mi], bhi[ni]);
                    mma_tf32(acc[mi][ni], ahi[mi], blo[ni]);
                }
        }

        if (more) {
            int nxt = cur ^ 1;
            *(float4*)&As[nxt][ar0 * ASTRIDE + akq]        = va0;
            *(float4*)&As[nxt][(ar0 + 64) * ASTRIDE + akq] = va1;
            *(float4*)&Bs[nxt][br0 * BSTRIDE + bnq]        = vb0;
            *(float4*)&Bs[nxt][(br0 + 8) * BSTRIDE + bnq]  = vb1;
            __syncthreads();
        }
    }

    if (EPI == 0) {
        #pragma unroll
        for (int mi = 0; mi < 4; mi++) {
            #pragma unroll
            for (int rr = 0; rr < 2; rr++) {
                int m = m0 + wm0 + mi * 16 + g + rr * 8;
                int b = m >> 11;
                int s = m & 2047;
                #pragma unroll
                for (int ni = 0; ni < 4; ni++) {
                    int n = n0 + wn0 + ni * 8 + 2 * c;
                    float x0 = acc[mi][ni][rr * 2];
                    float x1 = acc[mi][ni][rr * 2 + 1];
                    int part = n >> 10;
                    int d = n & 1023;
                    int h = d >> 6;
                    int e = d & 63;
                    size_t base = ((size_t)(b * H_ + h) * S_ + s) * HD_ + e;
                    if (part == 2) {
                        g_v[base] = x0; g_v[base + 1] = x1;
                    } else {
                        float co = g_cos[s * 32 + (e >> 1)];
                        float sn = g_sin[s * 32 + (e >> 1)];
                        float r0 = x0 * co - x1 * sn;
                        float r1 = x0 * sn + x1 * co;
                        if (part == 0) { g_q[base] = r0; g_q[base + 1] = r1; }
                        else           { g_k[base] = r0; g_k[base + 1] = r1; }
                    }
                }
            }
        }
    } else {
        #pragma unroll
        for (int mi = 0; mi < 4; mi++) {
            #pragma unroll
            for (int rr = 0; rr < 2; rr++) {
                int m = m0 + wm0 + mi * 16 + g + rr * 8;
                #pragma unroll
                for (int ni = 0; ni < 4; ni++) {
                    int n = n0 + wn0 + ni * 8 + 2 * c;
                    float2 o;
                    o.x = acc[mi][ni][rr * 2];
                    o.y = acc[mi][ni][rr * 2 + 1];
                    *(float2*)(Cout + (size_t)m * N + n) = o;
                }
            }
        }
    }
}

// ---------------- tensor-core flash attention --------------------------------
// Block: 256 threads = 8 warps; 128 q rows (16/warp), KV tiles of 128 keys.
// Warp owns rows [wq0, wq0+16) x all 128 keys -> softmax reduces within quad only.
// S = Q K^T via 3-term 3xTF32; O += P V via 2-term (P_tf32 x V_hi/V_lo).
// Smem (floats): Qs[128][68] | Ks[128][68] | Vs[128][72] | Ps[8][16][132] | pmb[128]
#define FA_SMEM_FLOATS (8704 + 8704 + 9216 + 16896 + 128)

__global__ __launch_bounds__(256) void flash_mma(const int* __restrict__ pm) {
    extern __shared__ float sm[];
    float* Qs  = sm;                 // stride 68
    float* Ks  = sm + 8704;          // stride 68
    float* Vs  = sm + 17408;         // stride 72
    float* Ps  = sm + 26624;         // per-warp [16][132]
    float* pmb = sm + 43520;         // additive mask bias

    int qb = (int)gridDim.x - 1 - (int)blockIdx.x;   // heavy blocks first
    int h = blockIdx.y, b = blockIdx.z;
    int tid = threadIdx.x, warp = tid >> 5, lane = tid & 31;
    int g = lane >> 2, c = lane & 3;
    int wq0 = warp * 16;
    float* Pw = Ps + warp * 16 * 132;

    const float* qg = g_q + ((size_t)((b * H_ + h) * S_) + qb * 128) * HD_;
    const float* kg = g_k + (size_t)((b * H_ + h) * S_) * HD_;
    const float* vg = g_v + (size_t)((b * H_ + h) * S_) * HD_;

    // load Q tile, pre-scaled
    #pragma unroll
    for (int i = 0; i < 8; i++) {
        int idx = tid + i * 256;          // 2048 float4
        int r = idx >> 4, c4 = (idx & 15) << 2;
        float4 t = *(const float4*)(qg + r * 64 + c4);
        Qs[r * 68 + c4 + 0] = t.x * SCALE;
        Qs[r * 68 + c4 + 1] = t.y * SCALE;
        Qs[r * 68 + c4 + 2] = t.z * SCALE;
        Qs[r * 68 + c4 + 3] = t.w * SCALE;
    }

    float o[8][4];
    #pragma unroll
    for (int nj = 0; nj < 8; nj++)
        #pragma unroll
        for (int r = 0; r < 4; r++) o[nj][r] = 0.f;
    float mrow0 = -1e30f, mrow1 = -1e30f, lsum0 = 0.f, lsum1 = 0.f;

    for (int kt = 0; kt <= qb; kt++) {
        // load K/V tiles + padding bias
        #pragma unroll
        for (int i = 0; i < 8; i++) {
            int idx = tid + i * 256;
            int r = idx >> 4, c4 = (idx & 15) << 2;
            float4 tk = *(const float4*)(kg + (size_t)(kt * 128 + r) * 64 + c4);
            float4 tv = *(const float4*)(vg + (size_t)(kt * 128 + r) * 64 + c4);
            *(float4*)&Ks[r * 68 + c4] = tk;
            *(float4*)&Vs[r * 72 + c4] = tv;
        }
        if (tid < 128) pmb[tid] = pm[b * S_ + kt * 128 + tid] ? 0.f : -3e30f;
        __syncthreads();

        // ---- S = Q K^T (3xTF32) ----
        float s[16][4];
        #pragma unroll
        for (int ni = 0; ni < 16; ni++)
            #pragma unroll
            for (int r = 0; r < 4; r++) s[ni][r] = 0.f;

        #pragma unroll
        for (int ks = 0; ks < 8; ks++) {
            uint32_t ah[4], al[4];
            {
                float f0 = Qs[(wq0 + g) * 68 + ks * 8 + c];
                float f1 = Qs[(wq0 + g + 8) * 68 + ks * 8 + c];
                float f2 = Qs[(wq0 + g) * 68 + ks * 8 + c + 4];
                float f3 = Qs[(wq0 + g + 8) * 68 + ks * 8 + c + 4];
                ah[0] = f2tf32(f0); al[0] = f2tf32(f0 - __uint_as_float(ah[0]));
                ah[1] = f2tf32(f1); al[1] = f2tf32(f1 - __uint_as_float(ah[1]));
                ah[2] = f2tf32(f2); al[2] = f2tf32(f2 - __uint_as_float(ah[2]));
                ah[3] = f2tf32(f3); al[3] = f2tf32(f3 - __uint_as_float(ah[3]));
            }
            #pragma unroll
            for (int ni = 0; ni < 16; ni++) {
                float f0 = Ks[(ni * 8 + g) * 68 + ks * 8 + c];
                float f1 = Ks[(ni * 8 + g) * 68 + ks * 8 + c + 4];
                uint32_t bh[2], bl[2];
                bh[0] = f2tf32(f0); bl[0] = f2tf32(f0 - __uint_as_float(bh[0]));
                bh[1] = f2tf32(f1); bl[1] = f2tf32(f1 - __uint_as_float(bh[1]));
                mma_tf32(s[ni], ah, bh);
                mma_tf32(s[ni], al, bh);
                mma_tf32(s[ni], ah, bl);
            }
        }

        // ---- mask + online softmax (quad-local) ----
        int r0 = wq0 + g, r1 = wq0 + g + 8;   // local rows (same offset as keys when kt==qb)
        bool diag = (kt == qb);
        float lmax0 = -3e30f, lmax1 = -3e30f;
        #pragma unroll
        for (int ni = 0; ni < 16; ni++) {
            int kl = ni * 8 + 2 * c;
            float b0 = pmb[kl], b1 = pmb[kl + 1];
            s[ni][0] += b0 + ((diag && kl     > r0) ? -3e30f : 0.f);
            s[ni][1] += b1 + ((diag && kl + 1 > r0) ? -3e30f : 0.f);
            s[ni][2] += b0 + ((diag && kl     > r1) ? -3e30f : 0.f);
            s[ni][3] += b1 + ((diag && kl + 1 > r1) ? -3e30f : 0.f);
            lmax0 = fmaxf(lmax0, fmaxf(s[ni][0], s[ni][1]));
            lmax1 = fmaxf(lmax1, fmaxf(s[ni][2], s[ni][3]));
        }
        lmax0 = fmaxf(lmax0, __shfl_xor_sync(0xffffffffu, lmax0, 1));
        lmax0 = fmaxf(lmax0, __shfl_xor_sync(0xffffffffu, lmax0, 2));
        lmax1 = fmaxf(lmax1, __shfl_xor_sync(0xffffffffu, lmax1, 1));
        lmax1 = fmaxf(lmax1, __shfl_xor_sync(0xffffffffu, lmax1, 2));

        float mn0 = fmaxf(mrow0, lmax0), mn1 = fmaxf(mrow1, lmax1);
        float al0 = __expf(mrow0 - mn0), al1 = __expf(mrow1 - mn1);
        float ps0 = 0.f, ps1 = 0.f;
        #pragma unroll
        for (int ni = 0; ni < 16; ni++) {
            float p0 = __expf(s[ni][0] - mn0);
            float p1 = __expf(s[ni][1] - mn0);
            float p2 = __expf(s[ni][2] - mn1);
            float p3 = __expf(s[ni][3] - mn1);
            ps0 += p0 + p1; ps1 += p2 + p3;
            float2 w0; w0.x = p0; w0.y = p1;
            float2 w1; w1.x = p2; w1.y = p3;
            *(float2*)&Pw[g * 132 + ni * 8 + 2 * c]       = w0;
            *(float2*)&Pw[(g + 8) * 132 + ni * 8 + 2 * c] = w1;
        }
        ps0 += __shfl_xor_sync(0xffffffffu, ps0, 1);
        ps0 += __shfl_xor_sync(0xffffffffu, ps0, 2);
        ps1 += __shfl_xor_sync(0xffffffffu, ps1, 1);
        ps1 += __shfl_xor_sync(0xffffffffu, ps1, 2);
        lsum0 = lsum0 * al0 + ps0;
        lsum1 = lsum1 * al1 + ps1;
        mrow0 = mn0; mrow1 = mn1;
        #pragma unroll
        for (int nj = 0; nj < 8; nj++) {
            o[nj][0] *= al0; o[nj][1] *= al0;
            o[nj][2] *= al1; o[nj][3] *= al1;
        }
        __syncwarp();

        // ---- O += P V (2-term) ----
        #pragma unroll
        for (int ks2 = 0; ks2 < 16; ks2++) {
            uint32_t pa[4];
            pa[0] = f2tf32(Pw[g * 132 + ks2 * 8 + c]);
            pa[1] = f2tf32(Pw[(g + 8) * 132 + ks2 * 8 + c]);
            pa[2] = f2tf32(Pw[g * 132 + ks2 * 8 + c + 4]);
            pa[3] = f2tf32(Pw[(g + 8) * 132 + ks2 * 8 + c + 4]);
            #pragma unroll
            for (int nj = 0; nj < 8; nj++) {
                float f0 = Vs[(ks2 * 8 + c) * 72 + nj * 8 + g];
                float f1 = Vs[(ks2 * 8 + c + 4) * 72 + nj * 8 + g];
                uint32_t vh[2], vl[2];
                vh[0] = f2tf32(f0); vl[0] = f2tf32(f0 - __uint_as_float(vh[0]));
                vh[1] = f2tf32(f1); vl[1] = f2tf32(f1 - __uint_as_float(vh[1]));
                mma_tf32(o[nj], pa, vh);
                mma_tf32(o[nj], pa, vl);
            }
        }
        __syncthreads();
    }

    float inv0 = 1.f / lsum0, inv1 = 1.f / lsum1;
    size_t row0 = (size_t)(b * S_ + qb * 128 + wq0 + g);
    float* op0 = g_attn + row0 * D_ + h * 64;
    float* op1 = g_attn + (row0 + 8) * D_ + h * 64;
    #pragma unroll
    for (int nj = 0; nj < 8; nj++) {
        float2 w0; w0.x = o[nj][0] * inv0; w0.y = o[nj][1] * inv0;
        float2 w1; w1.x = o[nj][2] * inv1; w1.y = o[nj][3] * inv1;
        *(float2*)(op0 + nj * 8 + 2 * c) = w0;
        *(float2*)(op1 + nj * 8 + 2 * c) = w1;
    }
}

// ---------------- launch ----------------------------------------------------
extern "C" void kernel_launch(void* const* d_in, const int* in_sizes, int n_in,
                              void* d_out, int out_size) {
    const float* x    = (const float*)d_in[0];
    const int*   pm   = (const int*)  d_in[1];
    const float* wqkv = (const float*)d_in[2];
    const float* wo   = (const float*)d_in[3];
    float* out = (float*)d_out;

    cudaFuncSetAttribute(flash_mma, cudaFuncAttributeMaxDynamicSharedMemorySize,
                         FA_SMEM_FLOATS * 4);

    rope_table_kernel<<<(S_ * 32 + 255) / 256, 256>>>();
    transpose_w<<<dim3(D_ / 32, NQKV / 32), dim3(32, 8)>>>(wqkv, NQKV, D_, 0);
    transpose_w<<<dim3(D_ / 32, D_  / 32), dim3(32, 8)>>>(wo,   D_,   D_, 1);

    mma_gemm<NQKV, 0><<<dim3(NQKV / 128, M_ / 128), 256>>>(x, nullptr);
    flash_mma<<<dim3(S_ / 128, H_, B_), 256, FA_SMEM_FLOATS * 4>>>(pm);
    mma_gemm<D_, 1><<<dim3(D_ / 128, M_ / 128), 256>>>(nullptr, out);
}

// round 10
// speedup vs baseline: 2.9001x; 1.0249x over previous
#include <cuda_runtime.h>
#include <math.h>
#include <stdint.h>

#define B_   4
#define S_   2048
#define D_   1024
#define H_   16
#define HD_  64
#define M_   (B_ * S_)      // 8192
#define NQKV (3 * D_)       // 3072
#define SCALE 0.125f        // 1/sqrt(64)

// ---------------- scratch (device globals; no runtime alloc allowed) --------
__device__ float g_wqkvT[D_ * NQKV];          // [K=1024][N=3072]
__device__ float g_woT  [D_ * D_];            // [K=1024][N=1024]
__device__ float g_q    [B_ * H_ * S_ * HD_]; // [B][H][S][64], rope applied
__device__ float g_k    [B_ * H_ * S_ * HD_];
__device__ float g_v    [B_ * H_ * S_ * HD_];
__device__ float g_attn [M_ * D_];            // [B*S][D]
__device__ float g_cos  [S_ * (HD_ / 2)];
__device__ float g_sin  [S_ * (HD_ / 2)];

// ---------------- RoPE table ------------------------------------------------
__global__ void rope_table_kernel() {
    int idx = blockIdx.x * blockDim.x + threadIdx.x;
    if (idx >= S_ * (HD_ / 2)) return;
    int s = idx >> 5;
    int i = idx & 31;
    double inv = exp(-(2.0 * (double)i / (double)HD_) * log(10000.0));
    double ang = (double)s * inv;
    g_cos[idx] = (float)cos(ang);
    g_sin[idx] = (float)sin(ang);
}

// ---------------- weight transpose: src[rows][cols] -> dst[cols][rows] ------
__global__ void transpose_w(const float* __restrict__ src, int rows, int cols, int which) {
    __shared__ float t[32][33];
    float* dst = which ? g_woT : g_wqkvT;
    int bx = blockIdx.x * 32;
    int by = blockIdx.y * 32;
    #pragma unroll
    for (int i = threadIdx.y; i < 32; i += 8) {
        t[i][threadIdx.x] = src[(by + i) * cols + bx + threadIdx.x];
    }
    __syncthreads();
    #pragma unroll
    for (int i = threadIdx.y; i < 32; i += 8) {
        int c = bx + i;
        int r = by + threadIdx.x;
        dst[c * rows + r] = t[threadIdx.x][i];
    }
}

// ---------------- tf32 helpers ----------------------------------------------
__device__ __forceinline__ uint32_t f2tf32(float x) {
    uint32_t r;
    asm("cvt.rna.tf32.f32 %0, %1;" : "=r"(r) : "f"(x));
    return r;
}

__device__ __forceinline__ void mma_tf32(float* d, const uint32_t* A, const uint32_t* Bv) {
    asm volatile(
        "mma.sync.aligned.m16n8k8.row.col.f32.tf32.tf32.f32 "
        "{%0,%1,%2,%3}, {%4,%5,%6,%7}, {%8,%9}, {%0,%1,%2,%3};\n"
        : "+f"(d[0]), "+f"(d[1]), "+f"(d[2]), "+f"(d[3])
        : "r"(A[0]), "r"(A[1]), "r"(A[2]), "r"(A[3]),
          "r"(Bv[0]), "r"(Bv[1]));
}

__device__ __forceinline__ void split4(float4 v, uint4& hi, uint4& lo) {
    hi.x = f2tf32(v.x); lo.x = f2tf32(v.x - __uint_as_float(hi.x));
    hi.y = f2tf32(v.y); lo.y = f2tf32(v.y - __uint_as_float(hi.y));
    hi.z = f2tf32(v.z); lo.z = f2tf32(v.z - __uint_as_float(hi.z));
    hi.w = f2tf32(v.w); lo.w = f2tf32(v.w - __uint_as_float(hi.w));
}

// ---------------- 3xTF32 GEMM, hi/lo pre-split in smem ----------------------
// Block tile 128(M) x 64(N), BK=16, 256 thr = 8 warps (4m x 2n), warp 32x32.
// Smem tiles store tf32 hi/lo (u32). A stride 20 (perm banks), B stride 72.
// 2 CTAs/SM via launch_bounds(256,2) -> regs <= 128.
#define ASTR 20
#define BSTR 72
#define G2_SMEM_U32 (10240 + 4608)   // A hi+lo (2buf x 2560 x2) + B hi+lo (2buf x 1152 x2)

template <int N, int EPI>
__global__ __launch_bounds__(256, 2) void mma_gemm2(const float* __restrict__ A_,
                                                    float* __restrict__ Cout) {
    const float* __restrict__ Bmat = (EPI == 0) ? g_wqkvT : g_woT;
    const float* __restrict__ A    = (EPI == 0) ? A_ : g_attn;

    extern __shared__ uint32_t smu[];
    uint32_t* Ah = smu;              // [2][128*ASTR]
    uint32_t* Al = Ah + 5120;
    uint32_t* Bh = Al + 5120;        // [2][16*BSTR]
    uint32_t* Bl = Bh + 2304;

    int tid  = threadIdx.x;
    int warp = tid >> 5, lane = tid & 31;
    int g = lane >> 2, c = lane & 3;
    int wm = (warp >> 1) * 32;      // 0,32,64,96
    int wn = (warp & 1) * 32;       // 0,32
    int m0 = blockIdx.y * 128;
    int n0 = blockIdx.x * 64;

    float acc[2][4][4];
    #pragma unroll
    for (int mi = 0; mi < 2; mi++)
        #pragma unroll
        for (int ni = 0; ni < 4; ni++)
            #pragma unroll
            for (int r = 0; r < 4; r++) acc[mi][ni][r] = 0.f;

    // loaders: A tile 128x16 -> 2 float4/thread; B tile 16x64 -> 1 float4/thread
    int ar0 = tid >> 2;             // 0..63
    int akq = (tid & 3) << 2;       // 0,4,8,12
    int br0 = tid >> 4;             // 0..15
    int bc  = (tid & 15) << 2;      // 0..60

    const float* aP = A    + (size_t)(m0 + ar0) * 1024 + akq;
    const float* bP = Bmat + (size_t)br0 * N + n0 + bc;

    // prologue chunk 0 -> buffer 0
    {
        uint4 h, l;
        split4(*(const float4*)(aP), h, l);
        *(uint4*)&Ah[ar0 * ASTR + akq] = h;
        *(uint4*)&Al[ar0 * ASTR + akq] = l;
        split4(*(const float4*)(aP + (size_t)64 * 1024), h, l);
        *(uint4*)&Ah[(ar0 + 64) * ASTR + akq] = h;
        *(uint4*)&Al[(ar0 + 64) * ASTR + akq] = l;
        split4(*(const float4*)(bP), h, l);
        *(uint4*)&Bh[br0 * BSTR + bc] = h;
        *(uint4*)&Bl[br0 * BSTR + bc] = l;
    }
    __syncthreads();

    for (int k0 = 0; k0 < 1024; k0 += 16) {
        int cur = (k0 >> 4) & 1;
        bool more = (k0 + 16) < 1024;
        float4 va0, va1, vb0;
        if (more) {
            va0 = *(const float4*)(aP + k0 + 16);
            va1 = *(const float4*)(aP + (size_t)64 * 1024 + k0 + 16);
            vb0 = *(const float4*)(bP + (size_t)(k0 + 16) * N);
        }

        const uint32_t* ah_ = Ah + cur * 2560;
        const uint32_t* al_ = Al + cur * 2560;
        const uint32_t* bh_ = Bh + cur * 1152;
        const uint32_t* bl_ = Bl + cur * 1152;
        #pragma unroll
        for (int kk = 0; kk < 16; kk += 8) {
            uint32_t ahi[2][4], alo[2][4], bhi[4][2], blo[4][2];
            #pragma unroll
            for (int mi = 0; mi < 2; mi++) {
                int r = wm + mi * 16 + g;
                ahi[mi][0] = ah_[r * ASTR + kk + c];
                ahi[mi][1] = ah_[(r + 8) * ASTR + kk + c];
                ahi[mi][2] = ah_[r * ASTR + kk + c + 4];
                ahi[mi][3] = ah_[(r + 8) * ASTR + kk + c + 4];
                alo[mi][0] = al_[r * ASTR + kk + c];
                alo[mi][1] = al_[(r + 8) * ASTR + kk + c];
                alo[mi][2] = al_[r * ASTR + kk + c + 4];
                alo[mi][3] = al_[(r + 8) * ASTR + kk + c + 4];
            }
            #pragma unroll
            for (int ni = 0; ni < 4; ni++) {
                int col = wn + ni * 8 + g;
                bhi[ni][0] = bh_[(kk + c) * BSTR + col];
                bhi[ni][1] = bh_[(kk + c + 4) * BSTR + col];
                blo[ni][0] = bl_[(kk + c) * BSTR + col];
                blo[ni][1] = bl_[(kk + c + 4) * BSTR + col];
            }
            #pragma unroll
            for (int mi = 0; mi < 2; mi++)
                #pragma unroll
                for (int ni = 0; ni < 4; ni++) {
                    mma_tf32(acc[mi][ni], ahi[mi], bhi[ni]);
                    mma_tf32(acc[mi][ni], alo[mi], bhi[ni]);
                    mma_tf32(acc[mi][ni], ahi[mi], blo[ni]);
                }
        }

        if (more) {
            int nxt = cur ^ 1;
            uint4 h, l;
            split4(va0, h, l);
            *(uint4*)&Ah[nxt * 2560 + ar0 * ASTR + akq] = h;
            *(uint4*)&Al[nxt * 2560 + ar0 * ASTR + akq] = l;
            split4(va1, h, l);
            *(uint4*)&Ah[nxt * 2560 + (ar0 + 64) * ASTR + akq] = h;
            *(uint4*)&Al[nxt * 2560 + (ar0 + 64) * ASTR + akq] = l;
            split4(vb0, h, l);
            *(uint4*)&Bh[nxt * 1152 + br0 * BSTR + bc] = h;
            *(uint4*)&Bl[nxt * 1152 + br0 * BSTR + bc] = l;
            __syncthreads();
        }
    }

    if (EPI == 0) {
        #pragma unroll
        for (int mi = 0; mi < 2; mi++) {
            #pragma unroll
            for (int rr = 0; rr < 2; rr++) {
                int m = m0 + wm + mi * 16 + g + rr * 8;
                int b = m >> 11;
                int s = m & 2047;
                #pragma unroll
                for (int ni = 0; ni < 4; ni++) {
                    int n = n0 + wn + ni * 8 + 2 * c;
                    float x0 = acc[mi][ni][rr * 2];
                    float x1 = acc[mi][ni][rr * 2 + 1];
                    int part = n >> 10;
                    int d = n & 1023;
                    int h = d >> 6;
                    int e = d & 63;
                    size_t base = ((size_t)(b * H_ + h) * S_ + s) * HD_ + e;
                    if (part == 2) {
                        g_v[base] = x0; g_v[base + 1] = x1;
                    } else {
                        float co = g_cos[s * 32 + (e >> 1)];
                        float sn = g_sin[s * 32 + (e >> 1)];
                        float r0 = x0 * co - x1 * sn;
                        float r1 = x0 * sn + x1 * co;
                        if (part == 0) { g_q[base] = r0; g_q[base + 1] = r1; }
                        else           { g_k[base] = r0; g_k[base + 1] = r1; }
                    }
                }
            }
        }
    } else {
        #pragma unroll
        for (int mi = 0; mi < 2; mi++) {
            #pragma unroll
            for (int rr = 0; rr < 2; rr++) {
                int m = m0 + wm + mi * 16 + g + rr * 8;
                #pragma unroll
                for (int ni = 0; ni < 4; ni++) {
                    int n = n0 + wn + ni * 8 + 2 * c;
                    float2 o;
                    o.x = acc[mi][ni][rr * 2];
                    o.y = acc[mi][ni][rr * 2 + 1];
                    *(float2*)(Cout + (size_t)m * N + n) = o;
                }
            }
        }
    }
}

// ---------------- tensor-core flash attention (unchanged) --------------------
#define FA_SMEM_FLOATS (8704 + 8704 + 9216 + 16896 + 128)

__global__ __launch_bounds__(256) void flash_mma(const int* __restrict__ pm) {
    extern __shared__ float sm[];
    float* Qs  = sm;                 // stride 68
    float* Ks  = sm + 8704;          // stride 68
    float* Vs  = sm + 17408;         // stride 72
    float* Ps  = sm + 26624;         // per-warp [16][132]
    float* pmb = sm + 43520;

    int qb = (int)gridDim.x - 1 - (int)blockIdx.x;
    int h = blockIdx.y, b = blockIdx.z;
    int tid = threadIdx.x, warp = tid >> 5, lane = tid & 31;
    int g = lane >> 2, c = lane & 3;
    int wq0 = warp * 16;
    float* Pw = Ps + warp * 16 * 132;

    const float* qg = g_q + ((size_t)((b * H_ + h) * S_) + qb * 128) * HD_;
    const float* kg = g_k + (size_t)((b * H_ + h) * S_) * HD_;
    const float* vg = g_v + (size_t)((b * H_ + h) * S_) * HD_;

    #pragma unroll
    for (int i = 0; i < 8; i++) {
        int idx = tid + i * 256;
        int r = idx >> 4, c4 = (idx & 15) << 2;
        float4 t = *(const float4*)(qg + r * 64 + c4);
        Qs[r * 68 + c4 + 0] = t.x * SCALE;
        Qs[r * 68 + c4 + 1] = t.y * SCALE;
        Qs[r * 68 + c4 + 2] = t.z * SCALE;
        Qs[r * 68 + c4 + 3] = t.w * SCALE;
    }

    float o[8][4];
    #pragma unroll
    for (int nj = 0; nj < 8; nj++)
        #pragma unroll
        for (int r = 0; r < 4; r++) o[nj][r] = 0.f;
    float mrow0 = -1e30f, mrow1 = -1e30f, lsum0 = 0.f, lsum1 = 0.f;

    for (int kt = 0; kt <= qb; kt++) {
        #pragma unroll
        for (int i = 0; i < 8; i++) {
            int idx = tid + i * 256;
            int r = idx >> 4, c4 = (idx & 15) << 2;
            float4 tk = *(const float4*)(kg + (size_t)(kt * 128 + r) * 64 + c4);
            float4 tv = *(const float4*)(vg + (size_t)(kt * 128 + r) * 64 + c4);
            *(float4*)&Ks[r * 68 + c4] = tk;
            *(float4*)&Vs[r * 72 + c4] = tv;
        }
        if (tid < 128) pmb[tid] = pm[b * S_ + kt * 128 + tid] ? 0.f : -3e30f;
        __syncthreads();

        float s[16][4];
        #pragma unroll
        for (int ni = 0; ni < 16; ni++)
            #pragma unroll
            for (int r = 0; r < 4; r++) s[ni][r] = 0.f;

        #pragma unroll
        for (int ks = 0; ks < 8; ks++) {
            uint32_t ah[4], al[4];
            {
                float f0 = Qs[(wq0 + g) * 68 + ks * 8 + c];
                float f1 = Qs[(wq0 + g + 8) * 68 + ks * 8 + c];
                float f2 = Qs[(wq0 + g) * 68 + ks * 8 + c + 4];
                float f3 = Qs[(wq0 + g + 8) * 68 + ks * 8 + c + 4];
                ah[0] = f2tf32(f0); al[0] = f2tf32(f0 - __uint_as_float(ah[0]));
                ah[1] = f2tf32(f1); al[1] = f2tf32(f1 - __uint_as_float(ah[1]));
                ah[2] = f2tf32(f2); al[2] = f2tf32(f2 - __uint_as_float(ah[2]));
                ah[3] = f2tf32(f3); al[3] = f2tf32(f3 - __uint_as_float(ah[3]));
            }
            #pragma unroll
            for (int ni = 0; ni < 16; ni++) {
                float f0 = Ks[(ni * 8 + g) * 68 + ks * 8 + c];
                float f1 = Ks[(ni * 8 + g) * 68 + ks * 8 + c + 4];
                uint32_t bh[2], bl[2];
                bh[0] = f2tf32(f0); bl[0] = f2tf32(f0 - __uint_as_float(bh[0]));
                bh[1] = f2tf32(f1); bl[1] = f2tf32(f1 - __uint_as_float(bh[1]));
                mma_tf32(s[ni], ah, bh);
                mma_tf32(s[ni], al, bh);
                mma_tf32(s[ni], ah, bl);
            }
        }

        int r0 = wq0 + g, r1 = wq0 + g + 8;
        bool diag = (kt == qb);
        float lmax0 = -3e30f, lmax1 = -3e30f;
        #pragma unroll
        for (int ni = 0; ni < 16; ni++) {
            int kl = ni * 8 + 2 * c;
            float b0 = pmb[kl], b1 = pmb[kl + 1];
            s[ni][0] += b0 + ((diag && kl     > r0) ? -3e30f : 0.f);
            s[ni][1] += b1 + ((diag && kl + 1 > r0) ? -3e30f : 0.f);
            s[ni][2] += b0 + ((diag && kl     > r1) ? -3e30f : 0.f);
            s[ni][3] += b1 + ((diag && kl + 1 > r1) ? -3e30f : 0.f);
            lmax0 = fmaxf(lmax0, fmaxf(s[ni][0], s[ni][1]));
            lmax1 = fmaxf(lmax1, fmaxf(s[ni][2], s[ni][3]));
        }
        lmax0 = fmaxf(lmax0, __shfl_xor_sync(0xffffffffu, lmax0, 1));
        lmax0 = fmaxf(lmax0, __shfl_xor_sync(0xffffffffu, lmax0, 2));
        lmax1 = fmaxf(lmax1, __shfl_xor_sync(0xffffffffu, lmax1, 1));
        lmax1 = fmaxf(lmax1, __shfl_xor_sync(0xffffffffu, lmax1, 2));

        float mn0 = fmaxf(mrow0, lmax0), mn1 = fmaxf(mrow1, lmax1);
        float al0 = __expf(mrow0 - mn0), al1 = __expf(mrow1 - mn1);
        float ps0 = 0.f, ps1 = 0.f;
        #pragma unroll
        for (int ni = 0; ni < 16; ni++) {
            float p0 = __expf(s[ni][0] - mn0);
            float p1 = __expf(s[ni][1] - mn0);
            float p2 = __expf(s[ni][2] - mn1);
            float p3 = __expf(s[ni][3] - mn1);
            ps0 += p0 + p1; ps1 += p2 + p3;
            float2 w0; w0.x = p0; w0.y = p1;
            float2 w1; w1.x = p2; w1.y = p3;
            *(float2*)&Pw[g * 132 + ni * 8 + 2 * c]       = w0;
            *(float2*)&Pw[(g + 8) * 132 + ni * 8 + 2 * c] = w1;
        }
        ps0 += __shfl_xor_sync(0xffffffffu, ps0, 1);
        ps0 += __shfl_xor_sync(0xffffffffu, ps0, 2);
        ps1 += __shfl_xor_sync(0xffffffffu, ps1, 1);
        ps1 += __shfl_xor_sync(0xffffffffu, ps1, 2);
        lsum0 = lsum0 * al0 + ps0;
        lsum1 = lsum1 * al1 + ps1;
        mrow0 = mn0; mrow1 = mn1;
        #pragma unroll
        for (int nj = 0; nj < 8; nj++) {
            o[nj][0] *= al0; o[nj][1] *= al0;
            o[nj][2] *= al1; o[nj][3] *= al1;
        }
        __syncwarp();

        #pragma unroll
        for (int ks2 = 0; ks2 < 16; ks2++) {
            uint32_t pa[4];
            pa[0] = f2tf32(Pw[g * 132 + ks2 * 8 + c]);
            pa[1] = f2tf32(Pw[(g + 8) * 132 + ks2 * 8 + c]);
            pa[2] = f2tf32(Pw[g * 132 + ks2 * 8 + c + 4]);
            pa[3] = f2tf32(Pw[(g + 8) * 132 + ks2 * 8 + c + 4]);
            #pragma unroll
            for (int nj = 0; nj < 8; nj++) {
                float f0 = Vs[(ks2 * 8 + c) * 72 + nj * 8 + g];
                float f1 = Vs[(ks2 * 8 + c + 4) * 72 + nj * 8 + g];
                uint32_t vh[2], vl[2];
                vh[0] = f2tf32(f0); vl[0] = f2tf32(f0 - __uint_as_float(vh[0]));
                vh[1] = f2tf32(f1); vl[1] = f2tf32(f1 - __uint_as_float(vh[1]));
                mma_tf32(o[nj], pa, vh);
                mma_tf32(o[nj], pa, vl);
            }
        }
        __syncthreads();
    }

    float inv0 = 1.f / lsum0, inv1 = 1.f / lsum1;
    size_t row0 = (size_t)(b * S_ + qb * 128 + wq0 + g);
    float* op0 = g_attn + row0 * D_ + h * 64;
    float* op1 = g_attn + (row0 + 8) * D_ + h * 64;
    #pragma unroll
    for (int nj = 0; nj < 8; nj++) {
        float2 w0; w0.x = o[nj][0] * inv0; w0.y = o[nj][1] * inv0;
        float2 w1; w1.x = o[nj][2] * inv1; w1.y = o[nj][3] * inv1;
        *(float2*)(op0 + nj * 8 + 2 * c) = w0;
        *(float2*)(op1 + nj * 8 + 2 * c) = w1;
    }
}

// ---------------- launch ----------------------------------------------------
extern "C" void kernel_launch(void* const* d_in, const int* in_sizes, int n_in,
                              void* d_out, int out_size) {
    const float* x    = (const float*)d_in[0];
    const int*   pm   = (const int*)  d_in[1];
    const float* wqkv = (const float*)d_in[2];
    const float* wo   = (const float*)d_in[3];
    float* out = (float*)d_out;

    cudaFuncSetAttribute(flash_mma, cudaFuncAttributeMaxDynamicSharedMemorySize,
                         FA_SMEM_FLOATS * 4);
    cudaFuncSetAttribute(mma_gemm2<NQKV, 0>,
                         cudaFuncAttributeMaxDynamicSharedMemorySize, G2_SMEM_U32 * 4);
    cudaFuncSetAttribute(mma_gemm2<D_, 1>,
                         cudaFuncAttributeMaxDynamicSharedMemorySize, G2_SMEM_U32 * 4);

    rope_table_kernel<<<(S_ * 32 + 255) / 256, 256>>>();
    transpose_w<<<dim3(D_ / 32, NQKV / 32), dim3(32, 8)>>>(wqkv, NQKV, D_, 0);
    transpose_w<<<dim3(D_ / 32, D_  / 32), dim3(32, 8)>>>(wo,   D_,   D_, 1);

    mma_gemm2<NQKV, 0><<<dim3(NQKV / 64, M_ / 128), 256, G2_SMEM_U32 * 4>>>(x, nullptr);
    flash_mma<<<dim3(S_ / 128, H_, B_), 256, FA_SMEM_FLOATS * 4>>>(pm);
    mma_gemm2<D_, 1><<<dim3(D_ / 64, M_ / 128), 256, G2_SMEM_U32 * 4>>>(nullptr, out);
}

// round 16
// speedup vs baseline: 3.9023x; 1.3456x over previous
#include <cuda_runtime.h>
#include <math.h>
#include <stdint.h>

#define B_   4
#define S_   2048
#define D_   1024
#define H_   16
#define HD_  64
#define M_   (B_ * S_)      // 8192
#define NQKV (3 * D_)       // 3072
#define SCALE 0.125f        // 1/sqrt(64)

// ---------------- scratch (device globals; no runtime alloc allowed) --------
__device__ float g_wqkvT[D_ * NQKV];          // [K=1024][N=3072]
__device__ float g_woT  [D_ * D_];            // [K=1024][N=1024]
__device__ float g_q    [B_ * H_ * S_ * HD_]; // [B][H][S][64], rope applied
__device__ float g_k    [B_ * H_ * S_ * HD_];
__device__ float g_v    [B_ * H_ * S_ * HD_];
__device__ float g_attn [M_ * D_];            // [B*S][D]
__device__ float g_cos  [S_ * (HD_ / 2)];
__device__ float g_sin  [S_ * (HD_ / 2)];

// ---------------- RoPE table ------------------------------------------------
__global__ void rope_table_kernel() {
    int idx = blockIdx.x * blockDim.x + threadIdx.x;
    if (idx >= S_ * (HD_ / 2)) return;
    int s = idx >> 5;
    int i = idx & 31;
    double inv = exp(-(2.0 * (double)i / (double)HD_) * log(10000.0));
    double ang = (double)s * inv;
    g_cos[idx] = (float)cos(ang);
    g_sin[idx] = (float)sin(ang);
}

// ---------------- weight transpose: src[rows][cols] -> dst[cols][rows] ------
__global__ void transpose_w(const float* __restrict__ src, int rows, int cols, int which) {
    __shared__ float t[32][33];
    float* dst = which ? g_woT : g_wqkvT;
    int bx = blockIdx.x * 32;
    int by = blockIdx.y * 32;
    #pragma unroll
    for (int i = threadIdx.y; i < 32; i += 8) {
        t[i][threadIdx.x] = src[(by + i) * cols + bx + threadIdx.x];
    }
    __syncthreads();
    #pragma unroll
    for (int i = threadIdx.y; i < 32; i += 8) {
        int c = bx + i;
        int r = by + threadIdx.x;
        dst[c * rows + r] = t[threadIdx.x][i];
    }
}

// ---------------- tf32 / bf16 helpers ----------------------------------------
__device__ __forceinline__ uint32_t f2tf32(float x) {
    uint32_t r;
    asm("cvt.rna.tf32.f32 %0, %1;" : "=r"(r) : "f"(x));
    return r;
}

__device__ __forceinline__ void mma_tf32(float* d, const uint32_t* A, const uint32_t* Bv) {
    asm volatile(
        "mma.sync.aligned.m16n8k8.row.col.f32.tf32.tf32.f32 "
        "{%0,%1,%2,%3}, {%4,%5,%6,%7}, {%8,%9}, {%0,%1,%2,%3};\n"
        : "+f"(d[0]), "+f"(d[1]), "+f"(d[2]), "+f"(d[3])
        : "r"(A[0]), "r"(A[1]), "r"(A[2]), "r"(A[3]),
          "r"(Bv[0]), "r"(Bv[1]));
}

__device__ __forceinline__ void mma_bf16(float* d, const uint32_t* A, const uint32_t* Bv) {
    asm volatile(
        "mma.sync.aligned.m16n8k16.row.col.f32.bf16.bf16.f32 "
        "{%0,%1,%2,%3}, {%4,%5,%6,%7}, {%8,%9}, {%0,%1,%2,%3};\n"
        : "+f"(d[0]), "+f"(d[1]), "+f"(d[2]), "+f"(d[3])
        : "r"(A[0]), "r"(A[1]), "r"(A[2]), "r"(A[3]),
          "r"(Bv[0]), "r"(Bv[1]));
}

// pack two floats to bf16x2: x0 -> low half, x1 -> high half
__device__ __forceinline__ uint32_t packbf(float x0, float x1) {
    uint32_t d;
    asm("cvt.rn.bf16x2.f32 %0, %1, %2;" : "=r"(d) : "f"(x1), "f"(x0));
    return d;
}
__device__ __forceinline__ float bflow(uint32_t u)  { return __uint_as_float(u << 16); }
__device__ __forceinline__ float bfhigh(uint32_t u) { return __uint_as_float(u & 0xffff0000u); }

// split float4 (4 consecutive k values) into 2 hi-pairs + 2 lo-pairs
__device__ __forceinline__ void split_bf4(float4 v, uint32_t* h, uint32_t* l) {
    uint32_t h0 = packbf(v.x, v.y);
    uint32_t h1 = packbf(v.z, v.w);
    h[0] = h0; h[1] = h1;
    l[0] = packbf(v.x - bflow(h0), v.y - bfhigh(h0));
    l[1] = packbf(v.z - bflow(h1), v.w - bfhigh(h1));
}

// ---------------- 3xBF16 GEMM (m16n8k16), hi/lo pre-split in smem ------------
// Block 128x128, BK=16, 256 thr = 8 warps (2m x 4n), warp tile 64x32.
// Smem u32 bf16-pairs: A [row][kpair] stride 12 (12g+c perm), B [kpair][col] stride 136.
#define APSTR 12
#define BPSTR 136

template <int N, int EPI>
__global__ __launch_bounds__(256, 2) void mma_gemm3(const float* __restrict__ A_,
                                                    float* __restrict__ Cout) {
    const float* __restrict__ Bmat = (EPI == 0) ? g_wqkvT : g_woT;
    const float* __restrict__ A    = (EPI == 0) ? A_ : g_attn;

    __shared__ uint32_t Ah[2][128 * APSTR];
    __shared__ uint32_t Al[2][128 * APSTR];
    __shared__ uint32_t Bh[2][8 * BPSTR];
    __shared__ uint32_t Bl[2][8 * BPSTR];

    int tid  = threadIdx.x;
    int warp = tid >> 5, lane = tid & 31;
    int g = lane >> 2, c = lane & 3;
    int wm = (warp >> 2) * 64;      // 0 or 64
    int wn = (warp & 3) * 32;       // 0,32,64,96
    int m0 = blockIdx.y * 128;
    int n0 = blockIdx.x * 128;

    float acc[4][4][4];
    #pragma unroll
    for (int mi = 0; mi < 4; mi++)
        #pragma unroll
        for (int ni = 0; ni < 4; ni++)
            #pragma unroll
            for (int r = 0; r < 4; r++) acc[mi][ni][r] = 0.f;

    // A loader: 128x16 floats; thread -> rows {ar0, ar0+64}, k quad (tid&3)*4
    int ar0 = tid >> 2;             // 0..63
    int akq = (tid & 3) << 2;       // 0,4,8,12
    int akp = (tid & 3) << 1;       // kpair 0,2,4,6
    // B loader: 16x128 floats; thread -> kpair bkp, col group bcg*4
    int bkp = tid >> 5;             // 0..7
    int bcg = (tid & 31) << 2;      // 0..124

    const float* aP = A    + (size_t)(m0 + ar0) * 1024 + akq;
    const float* bP = Bmat + (size_t)(2 * bkp) * N + n0 + bcg;

    // prologue: chunk 0 -> buffer 0
    {
        uint32_t h[2], l[2];
        split_bf4(*(const float4*)(aP), h, l);
        Ah[0][ar0 * APSTR + akp] = h[0]; Ah[0][ar0 * APSTR + akp + 1] = h[1];
        Al[0][ar0 * APSTR + akp] = l[0]; Al[0][ar0 * APSTR + akp + 1] = l[1];
        split_bf4(*(const float4*)(aP + (size_t)64 * 1024), h, l);
        Ah[0][(ar0 + 64) * APSTR + akp] = h[0]; Ah[0][(ar0 + 64) * APSTR + akp + 1] = h[1];
        Al[0][(ar0 + 64) * APSTR + akp] = l[0]; Al[0][(ar0 + 64) * APSTR + akp + 1] = l[1];
        float4 r0 = *(const float4*)(bP);
        float4 r1 = *(const float4*)(bP + N);
        #pragma unroll
        for (int j = 0; j < 4; j++) {
            float e0 = (&r0.x)[j], e1 = (&r1.x)[j];
            uint32_t hh = packbf(e0, e1);
            Bh[0][bkp * BPSTR + bcg + j] = hh;
            Bl[0][bkp * BPSTR + bcg + j] = packbf(e0 - bflow(hh), e1 - bfhigh(hh));
        }
    }
    __syncthreads();

    for (int k0 = 0; k0 < 1024; k0 += 16) {
        int cur = (k0 >> 4) & 1;
        bool more = (k0 + 16) < 1024;
        float4 va0, va1, vb0, vb1;
        if (more) {
            va0 = *(const float4*)(aP + k0 + 16);
            va1 = *(const float4*)(aP + (size_t)64 * 1024 + k0 + 16);
            vb0 = *(const float4*)(bP + (size_t)(k0 + 16) * N);
            vb1 = *(const float4*)(bP + (size_t)(k0 + 17) * N);
        }

        const uint32_t* ah_ = Ah[cur];
        const uint32_t* al_ = Al[cur];
        const uint32_t* bh_ = Bh[cur];
        const uint32_t* bl_ = Bl[cur];

        uint32_t ahi[4][4], alo[4][4];
        #pragma unroll
        for (int mi = 0; mi < 4; mi++) {
            int r = wm + mi * 16 + g;
            ahi[mi][0] = ah_[r * APSTR + c];
            ahi[mi][1] = ah_[(r + 8) * APSTR + c];
            ahi[mi][2] = ah_[r * APSTR + c + 4];
            ahi[mi][3] = ah_[(r + 8) * APSTR + c + 4];
            alo[mi][0] = al_[r * APSTR + c];
            alo[mi][1] = al_[(r + 8) * APSTR + c];
            alo[mi][2] = al_[r * APSTR + c + 4];
            alo[mi][3] = al_[(r + 8) * APSTR + c + 4];
        }
        #pragma unroll
        for (int ni = 0; ni < 4; ni++) {
            int col = wn + ni * 8 + g;
            uint32_t bhi[2], blo[2];
            bhi[0] = bh_[c * BPSTR + col];
            bhi[1] = bh_[(c + 4) * BPSTR + col];
            blo[0] = bl_[c * BPSTR + col];
            blo[1] = bl_[(c + 4) * BPSTR + col];
            #pragma unroll
            for (int mi = 0; mi < 4; mi++) {
                mma_bf16(acc[mi][ni], ahi[mi], bhi);   // hi*hi
                mma_bf16(acc[mi][ni], alo[mi], bhi);   // lo*hi
                mma_bf16(acc[mi][ni], ahi[mi], blo);   // hi*lo
            }
        }

        if (more) {
            int nxt = cur ^ 1;
            uint32_t h[2], l[2];
            split_bf4(va0, h, l);
            Ah[nxt][ar0 * APSTR + akp] = h[0]; Ah[nxt][ar0 * APSTR + akp + 1] = h[1];
            Al[nxt][ar0 * APSTR + akp] = l[0]; Al[nxt][ar0 * APSTR + akp + 1] = l[1];
            split_bf4(va1, h, l);
            Ah[nxt][(ar0 + 64) * APSTR + akp] = h[0]; Ah[nxt][(ar0 + 64) * APSTR + akp + 1] = h[1];
            Al[nxt][(ar0 + 64) * APSTR + akp] = l[0]; Al[nxt][(ar0 + 64) * APSTR + akp + 1] = l[1];
            #pragma unroll
            for (int j = 0; j < 4; j++) {
                float e0 = (&vb0.x)[j], e1 = (&vb1.x)[j];
                uint32_t hh = packbf(e0, e1);
                Bh[nxt][bkp * BPSTR + bcg + j] = hh;
                Bl[nxt][bkp * BPSTR + bcg + j] = packbf(e0 - bflow(hh), e1 - bfhigh(hh));
            }
            __syncthreads();
        }
    }

    if (EPI == 0) {
        #pragma unroll
        for (int mi = 0; mi < 4; mi++) {
            #pragma unroll
            for (int rr = 0; rr < 2; rr++) {
                int m = m0 + wm + mi * 16 + g + rr * 8;
                int b = m >> 11;
                int s = m & 2047;
                #pragma unroll
                for (int ni = 0; ni < 4; ni++) {
                    int n = n0 + wn + ni * 8 + 2 * c;
                    float x0 = acc[mi][ni][rr * 2];
                    float x1 = acc[mi][ni][rr * 2 + 1];
                    int part = n >> 10;
                    int d = n & 1023;
                    int h = d >> 6;
                    int e = d & 63;
                    size_t base = ((size_t)(b * H_ + h) * S_ + s) * HD_ + e;
                    if (part == 2) {
                        g_v[base] = x0; g_v[base + 1] = x1;
                    } else {
                        float co = g_cos[s * 32 + (e >> 1)];
                        float sn = g_sin[s * 32 + (e >> 1)];
                        float r0 = x0 * co - x1 * sn;
                        float r1 = x0 * sn + x1 * co;
                        if (part == 0) { g_q[base] = r0; g_q[base + 1] = r1; }
                        else           { g_k[base] = r0; g_k[base + 1] = r1; }
                    }
                }
            }
        }
    } else {
        #pragma unroll
        for (int mi = 0; mi < 4; mi++) {
            #pragma unroll
            for (int rr = 0; rr < 2; rr++) {
                int m = m0 + wm + mi * 16 + g + rr * 8;
                #pragma unroll
                for (int ni = 0; ni < 4; ni++) {
                    int n = n0 + wn + ni * 8 + 2 * c;
                    float2 o;
                    o.x = acc[mi][ni][rr * 2];
                    o.y = acc[mi][ni][rr * 2 + 1];
                    *(float2*)(Cout + (size_t)m * N + n) = o;
                }
            }
        }
    }
}

// ---------------- tensor-core flash attention (unchanged) --------------------
#define FA_SMEM_FLOATS (8704 + 8704 + 9216 + 16896 + 128)

__global__ __launch_bounds__(256) void flash_mma(const int* __restrict__ pm) {
    extern __shared__ float sm[];
    float* Qs  = sm;                 // stride 68
    float* Ks  = sm + 8704;          // stride 68
    float* Vs  = sm + 17408;         // stride 72
    float* Ps  = sm + 26624;         // per-warp [16][132]
    float* pmb = sm + 43520;

    int qb = (int)gridDim.x - 1 - (int)blockIdx.x;
    int h = blockIdx.y, b = blockIdx.z;
    int tid = threadIdx.x, warp = tid >> 5, lane = tid & 31;
    int g = lane >> 2, c = lane & 3;
    int wq0 = warp * 16;
    float* Pw = Ps + warp * 16 * 132;

    const float* qg = g_q + ((size_t)((b * H_ + h) * S_) + qb * 128) * HD_;
    const float* kg = g_k + (size_t)((b * H_ + h) * S_) * HD_;
    const float* vg = g_v + (size_t)((b * H_ + h) * S_) * HD_;

    #pragma unroll
    for (int i = 0; i < 8; i++) {
        int idx = tid + i * 256;
        int r = idx >> 4, c4 = (idx & 15) << 2;
        float4 t = *(const float4*)(qg + r * 64 + c4);
        Qs[r * 68 + c4 + 0] = t.x * SCALE;
        Qs[r * 68 + c4 + 1] = t.y * SCALE;
        Qs[r * 68 + c4 + 2] = t.z * SCALE;
        Qs[r * 68 + c4 + 3] = t.w * SCALE;
    }

    float o[8][4];
    #pragma unroll
    for (int nj = 0; nj < 8; nj++)
        #pragma unroll
        for (int r = 0; r < 4; r++) o[nj][r] = 0.f;
    float mrow0 = -1e30f, mrow1 = -1e30f, lsum0 = 0.f, lsum1 = 0.f;

    for (int kt = 0; kt <= qb; kt++) {
        #pragma unroll
        for (int i = 0; i < 8; i++) {
            int idx = tid + i * 256;
            int r = idx >> 4, c4 = (idx & 15) << 2;
            float4 tk = *(const float4*)(kg + (size_t)(kt * 128 + r) * 64 + c4);
            float4 tv = *(const float4*)(vg + (size_t)(kt * 128 + r) * 64 + c4);
            *(float4*)&Ks[r * 68 + c4] = tk;
            *(float4*)&Vs[r * 72 + c4] = tv;
        }
        if (tid < 128) pmb[tid] = pm[b * S_ + kt * 128 + tid] ? 0.f : -3e30f;
        __syncthreads();

        float s[16][4];
        #pragma unroll
        for (int ni = 0; ni < 16; ni++)
            #pragma unroll
            for (int r = 0; r < 4; r++) s[ni][r] = 0.f;

        #pragma unroll
        for (int ks = 0; ks < 8; ks++) {
            uint32_t ah[4], al[4];
            {
                float f0 = Qs[(wq0 + g) * 68 + ks * 8 + c];
                float f1 = Qs[(wq0 + g + 8) * 68 + ks * 8 + c];
                float f2 = Qs[(wq0 + g) * 68 + ks * 8 + c + 4];
                float f3 = Qs[(wq0 + g + 8) * 68 + ks * 8 + c + 4];
                ah[0] = f2tf32(f0); al[0] = f2tf32(f0 - __uint_as_float(ah[0]));
                ah[1] = f2tf32(f1); al[1] = f2tf32(f1 - __uint_as_float(ah[1]));
                ah[2] = f2tf32(f2); al[2] = f2tf32(f2 - __uint_as_float(ah[2]));
                ah[3] = f2tf32(f3); al[3] = f2tf32(f3 - __uint_as_float(ah[3]));
            }
            #pragma unroll
            for (int ni = 0; ni < 16; ni++) {
                float f0 = Ks[(ni * 8 + g) * 68 + ks * 8 + c];
                float f1 = Ks[(ni * 8 + g) * 68 + ks * 8 + c + 4];
                uint32_t bh[2], bl[2];
                bh[0] = f2tf32(f0); bl[0] = f2tf32(f0 - __uint_as_float(bh[0]));
                bh[1] = f2tf32(f1); bl[1] = f2tf32(f1 - __uint_as_float(bh[1]));
                mma_tf32(s[ni], ah, bh);
                mma_tf32(s[ni], al, bh);
                mma_tf32(s[ni], ah, bl);
            }
        }

        int r0 = wq0 + g, r1 = wq0 + g + 8;
        bool diag = (kt == qb);
        float lmax0 = -3e30f, lmax1 = -3e30f;
        #pragma unroll
        for (int ni = 0; ni < 16; ni++) {
            int kl = ni * 8 + 2 * c;
            float b0 = pmb[kl], b1 = pmb[kl + 1];
            s[ni][0] += b0 + ((diag && kl     > r0) ? -3e30f : 0.f);
            s[ni][1] += b1 + ((diag && kl + 1 > r0) ? -3e30f : 0.f);
            s[ni][2] += b0 + ((diag && kl     > r1) ? -3e30f : 0.f);
            s[ni][3] += b1 + ((diag && kl + 1 > r1) ? -3e30f : 0.f);
            lmax0 = fmaxf(lmax0, fmaxf(s[ni][0], s[ni][1]));
            lmax1 = fmaxf(lmax1, fmaxf(s[ni][2], s[ni][3]));
        }
        lmax0 = fmaxf(lmax0, __shfl_xor_sync(0xffffffffu, lmax0, 1));
        lmax0 = fmaxf(lmax0, __shfl_xor_sync(0xffffffffu, lmax0, 2));
        lmax1 = fmaxf(lmax1, __shfl_xor_sync(0xffffffffu, lmax1, 1));
        lmax1 = fmaxf(lmax1, __shfl_xor_sync(0xffffffffu, lmax1, 2));

        float mn0 = fmaxf(mrow0, lmax0), mn1 = fmaxf(mrow1, lmax1);
        float al0 = __expf(mrow0 - mn0), al1 = __expf(mrow1 - mn1);
        float ps0 = 0.f, ps1 = 0.f;
        #pragma unroll
        for (int ni = 0; ni < 16; ni++) {
            float p0 = __expf(s[ni][0] - mn0);
            float p1 = __expf(s[ni][1] - mn0);
            float p2 = __expf(s[ni][2] - mn1);
            float p3 = __expf(s[ni][3] - mn1);
            ps0 += p0 + p1; ps1 += p2 + p3;
            float2 w0; w0.x = p0; w0.y = p1;
            float2 w1; w1.x = p2; w1.y = p3;
            *(float2*)&Pw[g * 132 + ni * 8 + 2 * c]       = w0;
            *(float2*)&Pw[(g + 8) * 132 + ni * 8 + 2 * c] = w1;
        }
        ps0 += __shfl_xor_sync(0xffffffffu, ps0, 1);
        ps0 += __shfl_xor_sync(0xffffffffu, ps0, 2);
        ps1 += __shfl_xor_sync(0xffffffffu, ps1, 1);
        ps1 += __shfl_xor_sync(0xffffffffu, ps1, 2);
        lsum0 = lsum0 * al0 + ps0;
        lsum1 = lsum1 * al1 + ps1;
        mrow0 = mn0; mrow1 = mn1;
        #pragma unroll
        for (int nj = 0; nj < 8; nj++) {
            o[nj][0] *= al0; o[nj][1] *= al0;
            o[nj][2] *= al1; o[nj][3] *= al1;
        }
        __syncwarp();

        #pragma unroll
        for (int ks2 = 0; ks2 < 16; ks2++) {
            uint32_t pa[4];
            pa[0] = f2tf32(Pw[g * 132 + ks2 * 8 + c]);
            pa[1] = f2tf32(Pw[(g + 8) * 132 + ks2 * 8 + c]);
            pa[2] = f2tf32(Pw[g * 132 + ks2 * 8 + c + 4]);
            pa[3] = f2tf32(Pw[(g + 8) * 132 + ks2 * 8 + c + 4]);
            #pragma unroll
            for (int nj = 0; nj < 8; nj++) {
                float f0 = Vs[(ks2 * 8 + c) * 72 + nj * 8 + g];
                float f1 = Vs[(ks2 * 8 + c + 4) * 72 + nj * 8 + g];
                uint32_t vh[2], vl[2];
                vh[0] = f2tf32(f0); vl[0] = f2tf32(f0 - __uint_as_float(vh[0]));
                vh[1] = f2tf32(f1); vl[1] = f2tf32(f1 - __uint_as_float(vh[1]));
                mma_tf32(o[nj], pa, vh);
                mma_tf32(o[nj], pa, vl);
            }
        }
        __syncthreads();
    }

    float inv0 = 1.f / lsum0, inv1 = 1.f / lsum1;
    size_t row0 = (size_t)(b * S_ + qb * 128 + wq0 + g);
    float* op0 = g_attn + row0 * D_ + h * 64;
    float* op1 = g_attn + (row0 + 8) * D_ + h * 64;
    #pragma unroll
    for (int nj = 0; nj < 8; nj++) {
        float2 w0; w0.x = o[nj][0] * inv0; w0.y = o[nj][1] * inv0;
        float2 w1; w1.x = o[nj][2] * inv1; w1.y = o[nj][3] * inv1;
        *(float2*)(op0 + nj * 8 + 2 * c) = w0;
        *(float2*)(op1 + nj * 8 + 2 * c) = w1;
    }
}

// ---------------- launch ----------------------------------------------------
extern "C" void kernel_launch(void* const* d_in, const int* in_sizes, int n_in,
                              void* d_out, int out_size) {
    const float* x    = (const float*)d_in[0];
    const int*   pm   = (const int*)  d_in[1];
    const float* wqkv = (const float*)d_in[2];
    const float* wo   = (const float*)d_in[3];
    float* out = (float*)d_out;

    cudaFuncSetAttribute(flash_mma, cudaFuncAttributeMaxDynamicSharedMemorySize,
                         FA_SMEM_FLOATS * 4);

    rope_table_kernel<<<(S_ * 32 + 255) / 256, 256>>>();
    transpose_w<<<dim3(D_ / 32, NQKV / 32), dim3(32, 8)>>>(wqkv, NQKV, D_, 0);
    transpose_w<<<dim3(D_ / 32, D_  / 32), dim3(32, 8)>>>(wo,   D_,   D_, 1);

    mma_gemm3<NQKV, 0><<<dim3(NQKV / 128, M_ / 128), 256>>>(x, nullptr);
    flash_mma<<<dim3(S_ / 128, H_, B_), 256, FA_SMEM_FLOATS * 4>>>(pm);
    mma_gemm3<D_, 1><<<dim3(D_ / 128, M_ / 128), 256>>>(nullptr, out);
}

// round 17
// speedup vs baseline: 5.1963x; 1.3316x over previous
#include <cuda_runtime.h>
#include <math.h>
#include <stdint.h>

#define B_   4
#define S_   2048
#define D_   1024
#define H_   16
#define HD_  64
#define M_   (B_ * S_)      // 8192
#define NQKV (3 * D_)       // 3072
#define SCALE 0.125f        // 1/sqrt(64)

// ---------------- scratch (device globals; no runtime alloc allowed) --------
__device__ float g_wqkvT[D_ * NQKV];          // [K=1024][N=3072]
__device__ float g_woT  [D_ * D_];            // [K=1024][N=1024]
__device__ float g_q    [B_ * H_ * S_ * HD_]; // [B][H][S][64], rope applied
__device__ float g_k    [B_ * H_ * S_ * HD_];
__device__ float g_v    [B_ * H_ * S_ * HD_];
__device__ float g_attn [M_ * D_];            // [B*S][D]
__device__ float g_cos  [S_ * (HD_ / 2)];
__device__ float g_sin  [S_ * (HD_ / 2)];

// ---------------- RoPE table ------------------------------------------------
__global__ void rope_table_kernel() {
    int idx = blockIdx.x * blockDim.x + threadIdx.x;
    if (idx >= S_ * (HD_ / 2)) return;
    int s = idx >> 5;
    int i = idx & 31;
    double inv = exp(-(2.0 * (double)i / (double)HD_) * log(10000.0));
    double ang = (double)s * inv;
    g_cos[idx] = (float)cos(ang);
    g_sin[idx] = (float)sin(ang);
}

// ---------------- weight transpose: src[rows][cols] -> dst[cols][rows] ------
__global__ void transpose_w(const float* __restrict__ src, int rows, int cols, int which) {
    __shared__ float t[32][33];
    float* dst = which ? g_woT : g_wqkvT;
    int bx = blockIdx.x * 32;
    int by = blockIdx.y * 32;
    #pragma unroll
    for (int i = threadIdx.y; i < 32; i += 8) {
        t[i][threadIdx.x] = src[(by + i) * cols + bx + threadIdx.x];
    }
    __syncthreads();
    #pragma unroll
    for (int i = threadIdx.y; i < 32; i += 8) {
        int c = bx + i;
        int r = by + threadIdx.x;
        dst[c * rows + r] = t[threadIdx.x][i];
    }
}

// ---------------- bf16 helpers ----------------------------------------------
__device__ __forceinline__ void mma_bf16(float* d, const uint32_t* A, const uint32_t* Bv) {
    asm volatile(
        "mma.sync.aligned.m16n8k16.row.col.f32.bf16.bf16.f32 "
        "{%0,%1,%2,%3}, {%4,%5,%6,%7}, {%8,%9}, {%0,%1,%2,%3};\n"
        : "+f"(d[0]), "+f"(d[1]), "+f"(d[2]), "+f"(d[3])
        : "r"(A[0]), "r"(A[1]), "r"(A[2]), "r"(A[3]),
          "r"(Bv[0]), "r"(Bv[1]));
}

// pack two floats to bf16x2: x0 -> low half, x1 -> high half
__device__ __forceinline__ uint32_t packbf(float x0, float x1) {
    uint32_t d;
    asm("cvt.rn.bf16x2.f32 %0, %1, %2;" : "=r"(d) : "f"(x1), "f"(x0));
    return d;
}
__device__ __forceinline__ float bflow(uint32_t u)  { return __uint_as_float(u << 16); }
__device__ __forceinline__ float bfhigh(uint32_t u) { return __uint_as_float(u & 0xffff0000u); }

// split float4 (4 consecutive k values) into 2 hi-pairs + 2 lo-pairs
__device__ __forceinline__ void split_bf4(float4 v, uint32_t* h, uint32_t* l) {
    uint32_t h0 = packbf(v.x, v.y);
    uint32_t h1 = packbf(v.z, v.w);
    h[0] = h0; h[1] = h1;
    l[0] = packbf(v.x - bflow(h0), v.y - bfhigh(h0));
    l[1] = packbf(v.z - bflow(h1), v.w - bfhigh(h1));
}

// ---------------- 3xBF16 GEMM (m16n8k16), hi/lo pre-split in smem ------------
// Block 128x128, BK=16, 256 thr = 8 warps (2m x 4n), warp tile 64x32.
#define APSTR 12
#define BPSTR 136

template <int N, int EPI>
__global__ __launch_bounds__(256, 2) void mma_gemm3(const float* __restrict__ A_,
                                                    float* __restrict__ Cout) {
    const float* __restrict__ Bmat = (EPI == 0) ? g_wqkvT : g_woT;
    const float* __restrict__ A    = (EPI == 0) ? A_ : g_attn;

    __shared__ uint32_t Ah[2][128 * APSTR];
    __shared__ uint32_t Al[2][128 * APSTR];
    __shared__ uint32_t Bh[2][8 * BPSTR];
    __shared__ uint32_t Bl[2][8 * BPSTR];

    int tid  = threadIdx.x;
    int warp = tid >> 5, lane = tid & 31;
    int g = lane >> 2, c = lane & 3;
    int wm = (warp >> 2) * 64;      // 0 or 64
    int wn = (warp & 3) * 32;       // 0,32,64,96
    int m0 = blockIdx.y * 128;
    int n0 = blockIdx.x * 128;

    float acc[4][4][4];
    #pragma unroll
    for (int mi = 0; mi < 4; mi++)
        #pragma unroll
        for (int ni = 0; ni < 4; ni++)
            #pragma unroll
            for (int r = 0; r < 4; r++) acc[mi][ni][r] = 0.f;

    int ar0 = tid >> 2;             // 0..63
    int akq = (tid & 3) << 2;       // 0,4,8,12
    int akp = (tid & 3) << 1;       // kpair 0,2,4,6
    int bkp = tid >> 5;             // 0..7
    int bcg = (tid & 31) << 2;      // 0..124

    const float* aP = A    + (size_t)(m0 + ar0) * 1024 + akq;
    const float* bP = Bmat + (size_t)(2 * bkp) * N + n0 + bcg;

    {
        uint32_t h[2], l[2];
        split_bf4(*(const float4*)(aP), h, l);
        Ah[0][ar0 * APSTR + akp] = h[0]; Ah[0][ar0 * APSTR + akp + 1] = h[1];
        Al[0][ar0 * APSTR + akp] = l[0]; Al[0][ar0 * APSTR + akp + 1] = l[1];
        split_bf4(*(const float4*)(aP + (size_t)64 * 1024), h, l);
        Ah[0][(ar0 + 64) * APSTR + akp] = h[0]; Ah[0][(ar0 + 64) * APSTR + akp + 1] = h[1];
        Al[0][(ar0 + 64) * APSTR + akp] = l[0]; Al[0][(ar0 + 64) * APSTR + akp + 1] = l[1];
        float4 r0 = *(const float4*)(bP);
        float4 r1 = *(const float4*)(bP + N);
        #pragma unroll
        for (int j = 0; j < 4; j++) {
            float e0 = (&r0.x)[j], e1 = (&r1.x)[j];
            uint32_t hh = packbf(e0, e1);
            Bh[0][bkp * BPSTR + bcg + j] = hh;
            Bl[0][bkp * BPSTR + bcg + j] = packbf(e0 - bflow(hh), e1 - bfhigh(hh));
        }
    }
    __syncthreads();

    for (int k0 = 0; k0 < 1024; k0 += 16) {
        int cur = (k0 >> 4) & 1;
        bool more = (k0 + 16) < 1024;
        float4 va0, va1, vb0, vb1;
        if (more) {
            va0 = *(const float4*)(aP + k0 + 16);
            va1 = *(const float4*)(aP + (size_t)64 * 1024 + k0 + 16);
            vb0 = *(const float4*)(bP + (size_t)(k0 + 16) * N);
            vb1 = *(const float4*)(bP + (size_t)(k0 + 17) * N);
        }

        const uint32_t* ah_ = Ah[cur];
        const uint32_t* al_ = Al[cur];
        const uint32_t* bh_ = Bh[cur];
        const uint32_t* bl_ = Bl[cur];

        uint32_t ahi[4][4], alo[4][4];
        #pragma unroll
        for (int mi = 0; mi < 4; mi++) {
            int r = wm + mi * 16 + g;
            ahi[mi][0] = ah_[r * APSTR + c];
            ahi[mi][1] = ah_[(r + 8) * APSTR + c];
            ahi[mi][2] = ah_[r * APSTR + c + 4];
            ahi[mi][3] = ah_[(r + 8) * APSTR + c + 4];
            alo[mi][0] = al_[r * APSTR + c];
            alo[mi][1] = al_[(r + 8) * APSTR + c];
            alo[mi][2] = al_[r * APSTR + c + 4];
            alo[mi][3] = al_[(r + 8) * APSTR + c + 4];
        }
        #pragma unroll
        for (int ni = 0; ni < 4; ni++) {
            int col = wn + ni * 8 + g;
            uint32_t bhi[2], blo[2];
            bhi[0] = bh_[c * BPSTR + col];
            bhi[1] = bh_[(c + 4) * BPSTR + col];
            blo[0] = bl_[c * BPSTR + col];
            blo[1] = bl_[(c + 4) * BPSTR + col];
            #pragma unroll
            for (int mi = 0; mi < 4; mi++) {
                mma_bf16(acc[mi][ni], ahi[mi], bhi);   // hi*hi
                mma_bf16(acc[mi][ni], alo[mi], bhi);   // lo*hi
                mma_bf16(acc[mi][ni], ahi[mi], blo);   // hi*lo
            }
        }

        if (more) {
            int nxt = cur ^ 1;
            uint32_t h[2], l[2];
            split_bf4(va0, h, l);
            Ah[nxt][ar0 * APSTR + akp] = h[0]; Ah[nxt][ar0 * APSTR + akp + 1] = h[1];
            Al[nxt][ar0 * APSTR + akp] = l[0]; Al[nxt][ar0 * APSTR + akp + 1] = l[1];
            split_bf4(va1, h, l);
            Ah[nxt][(ar0 + 64) * APSTR + akp] = h[0]; Ah[nxt][(ar0 + 64) * APSTR + akp + 1] = h[1];
            Al[nxt][(ar0 + 64) * APSTR + akp] = l[0]; Al[nxt][(ar0 + 64) * APSTR + akp + 1] = l[1];
            #pragma unroll
            for (int j = 0; j < 4; j++) {
                float e0 = (&vb0.x)[j], e1 = (&vb1.x)[j];
                uint32_t hh = packbf(e0, e1);
                Bh[nxt][bkp * BPSTR + bcg + j] = hh;
                Bl[nxt][bkp * BPSTR + bcg + j] = packbf(e0 - bflow(hh), e1 - bfhigh(hh));
            }
            __syncthreads();
        }
    }

    if (EPI == 0) {
        #pragma unroll
        for (int mi = 0; mi < 4; mi++) {
            #pragma unroll
            for (int rr = 0; rr < 2; rr++) {
                int m = m0 + wm + mi * 16 + g + rr * 8;
                int b = m >> 11;
                int s = m & 2047;
                #pragma unroll
                for (int ni = 0; ni < 4; ni++) {
                    int n = n0 + wn + ni * 8 + 2 * c;
                    float x0 = acc[mi][ni][rr * 2];
                    float x1 = acc[mi][ni][rr * 2 + 1];
                    int part = n >> 10;
                    int d = n & 1023;
                    int h = d >> 6;
                    int e = d & 63;
                    size_t base = ((size_t)(b * H_ + h) * S_ + s) * HD_ + e;
                    if (part == 2) {
                        g_v[base] = x0; g_v[base + 1] = x1;
                    } else {
                        float co = g_cos[s * 32 + (e >> 1)];
                        float sn = g_sin[s * 32 + (e >> 1)];
                        float r0 = x0 * co - x1 * sn;
                        float r1 = x0 * sn + x1 * co;
                        if (part == 0) { g_q[base] = r0; g_q[base + 1] = r1; }
                        else           { g_k[base] = r0; g_k[base + 1] = r1; }
                    }
                }
            }
        }
    } else {
        #pragma unroll
        for (int mi = 0; mi < 4; mi++) {
            #pragma unroll
            for (int rr = 0; rr < 2; rr++) {
                int m = m0 + wm + mi * 16 + g + rr * 8;
                #pragma unroll
                for (int ni = 0; ni < 4; ni++) {
                    int n = n0 + wn + ni * 8 + 2 * c;
                    float2 o;
                    o.x = acc[mi][ni][rr * 2];
                    o.y = acc[mi][ni][rr * 2 + 1];
                    *(float2*)(Cout + (size_t)m * N + n) = o;
                }
            }
        }
    }
}

// ---------------- bf16 tensor-core flash attention ---------------------------
// Block: 256 thr = 8 warps, 128 q rows (16/warp), KV tiles of 128 keys.
// All operands pre-split bf16 hi/lo pairs in smem.
// Smem u32 layout: Qh[128*36] Ql Kh[128*36] Kl Vh[64*72] Vl Ph[8704] Pl pmb[128]
#define QKSTR 36
#define VSTR  72
#define PSTR  68
#define OFF_QH 0
#define OFF_QL 4608
#define OFF_KH 9216
#define OFF_KL 13824
#define OFF_VH 18432
#define OFF_VL 23040
#define OFF_PH 27648
#define OFF_PL 36352
#define OFF_PM 45056
#define FB_SMEM_U32 (45056 + 128)

__global__ __launch_bounds__(256) void flash_bf16(const int* __restrict__ pm) {
    extern __shared__ uint32_t su[];
    uint32_t* Qh = su + OFF_QH;
    uint32_t* Ql = su + OFF_QL;
    uint32_t* Kh = su + OFF_KH;
    uint32_t* Kl = su + OFF_KL;
    uint32_t* Vh = su + OFF_VH;
    uint32_t* Vl = su + OFF_VL;
    float*   pmb = (float*)(su + OFF_PM);

    int qb = (int)gridDim.x - 1 - (int)blockIdx.x;   // heavy blocks first
    int h = blockIdx.y, b = blockIdx.z;
    int tid = threadIdx.x, warp = tid >> 5, lane = tid & 31;
    int g = lane >> 2, c = lane & 3;
    int wq0 = warp * 16;
    uint32_t* Phw = su + OFF_PH + warp * 16 * PSTR;
    uint32_t* Plw = su + OFF_PL + warp * 16 * PSTR;

    const float* qg = g_q + ((size_t)((b * H_ + h) * S_) + qb * 128) * HD_;
    const float* kg = g_k + (size_t)((b * H_ + h) * S_) * HD_;
    const float* vg = g_v + (size_t)((b * H_ + h) * S_) * HD_;

    // load Q tile once: scale, split to bf16 hi/lo pairs along head dim
    #pragma unroll
    for (int i = 0; i < 8; i++) {
        int idx = tid + i * 256;          // 2048 float4
        int r = idx >> 4, c4 = (idx & 15) << 2;
        float4 t = *(const float4*)(qg + r * 64 + c4);
        t.x *= SCALE; t.y *= SCALE; t.z *= SCALE; t.w *= SCALE;
        uint32_t hh[2], ll[2];
        split_bf4(t, hh, ll);
        int p = r * QKSTR + (c4 >> 1);
        Qh[p] = hh[0]; Qh[p + 1] = hh[1];
        Ql[p] = ll[0]; Ql[p + 1] = ll[1];
    }

    float o[8][4];
    #pragma unroll
    for (int nj = 0; nj < 8; nj++)
        #pragma unroll
        for (int r = 0; r < 4; r++) o[nj][r] = 0.f;
    float mrow0 = -1e30f, mrow1 = -1e30f, lsum0 = 0.f, lsum1 = 0.f;

    for (int kt = 0; kt <= qb; kt++) {
        // K tile: pairs along head dim
        #pragma unroll
        for (int i = 0; i < 8; i++) {
            int idx = tid + i * 256;
            int r = idx >> 4, c4 = (idx & 15) << 2;
            float4 t = *(const float4*)(kg + (size_t)(kt * 128 + r) * 64 + c4);
            uint32_t hh[2], ll[2];
            split_bf4(t, hh, ll);
            int p = r * QKSTR + (c4 >> 1);
            Kh[p] = hh[0]; Kh[p + 1] = hh[1];
            Kl[p] = ll[0]; Kl[p + 1] = ll[1];
        }
        // V tile: pairs along KEY dim (two keys packed per u32, per head dim)
        #pragma unroll
        for (int i = 0; i < 4; i++) {
            int idx = tid + i * 256;          // 1024 items
            int kp = idx >> 4, dg = (idx & 15) << 2;
            const float* v0 = vg + (size_t)(kt * 128 + 2 * kp) * 64 + dg;
            float4 a = *(const float4*)(v0);
            float4 bb = *(const float4*)(v0 + 64);
            #pragma unroll
            for (int j = 0; j < 4; j++) {
                float e0 = (&a.x)[j], e1 = (&bb.x)[j];
                uint32_t hh = packbf(e0, e1);
                Vh[kp * VSTR + dg + j] = hh;
                Vl[kp * VSTR + dg + j] = packbf(e0 - bflow(hh), e1 - bfhigh(hh));
            }
        }
        if (tid < 128) pmb[tid] = pm[b * S_ + kt * 128 + tid] ? 0.f : -3e30f;
        __syncthreads();

        // ---- S = Q K^T (3xBF16, m16n8k16, 4 k-steps) ----
        float s[16][4];
        #pragma unroll
        for (int ni = 0; ni < 16; ni++)
            #pragma unroll
            for (int r = 0; r < 4; r++) s[ni][r] = 0.f;

        int qrow  = (wq0 + g) * QKSTR;
        int qrow8 = (wq0 + g + 8) * QKSTR;
        #pragma unroll
        for (int ks = 0; ks < 4; ks++) {
            uint32_t ah[4], al[4];
            ah[0] = Qh[qrow  + ks * 8 + c];
            ah[1] = Qh[qrow8 + ks * 8 + c];
            ah[2] = Qh[qrow  + ks * 8 + c + 4];
            ah[3] = Qh[qrow8 + ks * 8 + c + 4];
            al[0] = Ql[qrow  + ks * 8 + c];
            al[1] = Ql[qrow8 + ks * 8 + c];
            al[2] = Ql[qrow  + ks * 8 + c + 4];
            al[3] = Ql[qrow8 + ks * 8 + c + 4];
            #pragma unroll
            for (int ni = 0; ni < 16; ni++) {
                int kb = (ni * 8 + g) * QKSTR + ks * 8;
                uint32_t bh[2], bl[2];
                bh[0] = Kh[kb + c];
                bh[1] = Kh[kb + c + 4];
                bl[0] = Kl[kb + c];
                bl[1] = Kl[kb + c + 4];
                mma_bf16(s[ni], ah, bh);
                mma_bf16(s[ni], al, bh);
                mma_bf16(s[ni], ah, bl);
            }
        }

        // ---- mask + online softmax (quad-local) ----
        int r0 = wq0 + g, r1 = wq0 + g + 8;
        bool diag = (kt == qb);
        float lmax0 = -3e30f, lmax1 = -3e30f;
        #pragma unroll
        for (int ni = 0; ni < 16; ni++) {
            int kl = ni * 8 + 2 * c;
            float b0 = pmb[kl], b1 = pmb[kl + 1];
            s[ni][0] += b0 + ((diag && kl     > r0) ? -3e30f : 0.f);
            s[ni][1] += b1 + ((diag && kl + 1 > r0) ? -3e30f : 0.f);
            s[ni][2] += b0 + ((diag && kl     > r1) ? -3e30f : 0.f);
            s[ni][3] += b1 + ((diag && kl + 1 > r1) ? -3e30f : 0.f);
            lmax0 = fmaxf(lmax0, fmaxf(s[ni][0], s[ni][1]));
            lmax1 = fmaxf(lmax1, fmaxf(s[ni][2], s[ni][3]));
        }
        lmax0 = fmaxf(lmax0, __shfl_xor_sync(0xffffffffu, lmax0, 1));
        lmax0 = fmaxf(lmax0, __shfl_xor_sync(0xffffffffu, lmax0, 2));
        lmax1 = fmaxf(lmax1, __shfl_xor_sync(0xffffffffu, lmax1, 1));
        lmax1 = fmaxf(lmax1, __shfl_xor_sync(0xffffffffu, lmax1, 2));

        float mn0 = fmaxf(mrow0, lmax0), mn1 = fmaxf(mrow1, lmax1);
        float al0 = __expf(mrow0 - mn0), al1 = __expf(mrow1 - mn1);
        float ps0 = 0.f, ps1 = 0.f;
        #pragma unroll
        for (int ni = 0; ni < 16; ni++) {
            float p0 = __expf(s[ni][0] - mn0);
            float p1 = __expf(s[ni][1] - mn0);
            float p2 = __expf(s[ni][2] - mn1);
            float p3 = __expf(s[ni][3] - mn1);
            ps0 += p0 + p1; ps1 += p2 + p3;
            int pp = ni * 4 + c;
            uint32_t h0 = packbf(p0, p1);
            uint32_t h1 = packbf(p2, p3);
            Phw[g * PSTR + pp]       = h0;
            Phw[(g + 8) * PSTR + pp] = h1;
            Plw[g * PSTR + pp]       = packbf(p0 - bflow(h0), p1 - bfhigh(h0));
            Plw[(g + 8) * PSTR + pp] = packbf(p2 - bflow(h1), p3 - bfhigh(h1));
        }
        ps0 += __shfl_xor_sync(0xffffffffu, ps0, 1);
        ps0 += __shfl_xor_sync(0xffffffffu, ps0, 2);
        ps1 += __shfl_xor_sync(0xffffffffu, ps1, 1);
        ps1 += __shfl_xor_sync(0xffffffffu, ps1, 2);
        lsum0 = lsum0 * al0 + ps0;
        lsum1 = lsum1 * al1 + ps1;
        mrow0 = mn0; mrow1 = mn1;
        #pragma unroll
        for (int nj = 0; nj < 8; nj++) {
            o[nj][0] *= al0; o[nj][1] *= al0;
            o[nj][2] *= al1; o[nj][3] *= al1;
        }
        __syncwarp();

        // ---- O += P V (3-term bf16, 8 k-steps over 128 keys) ----
        #pragma unroll
        for (int ks2 = 0; ks2 < 8; ks2++) {
            uint32_t pah[4], pal[4];
            pah[0] = Phw[g * PSTR + ks2 * 8 + c];
            pah[1] = Phw[(g + 8) * PSTR + ks2 * 8 + c];
            pah[2] = Phw[g * PSTR + ks2 * 8 + c + 4];
            pah[3] = Phw[(g + 8) * PSTR + ks2 * 8 + c + 4];
            pal[0] = Plw[g * PSTR + ks2 * 8 + c];
            pal[1] = Plw[(g + 8) * PSTR + ks2 * 8 + c];
            pal[2] = Plw[g * PSTR + ks2 * 8 + c + 4];
            pal[3] = Plw[(g + 8) * PSTR + ks2 * 8 + c + 4];
            #pragma unroll
            for (int nj = 0; nj < 8; nj++) {
                uint32_t vh[2], vl[2];
                vh[0] = Vh[(ks2 * 8 + c) * VSTR + nj * 8 + g];
                vh[1] = Vh[(ks2 * 8 + c + 4) * VSTR + nj * 8 + g];
                vl[0] = Vl[(ks2 * 8 + c) * VSTR + nj * 8 + g];
                vl[1] = Vl[(ks2 * 8 + c + 4) * VSTR + nj * 8 + g];
                mma_bf16(o[nj], pah, vh);
                mma_bf16(o[nj], pal, vh);
                mma_bf16(o[nj], pah, vl);
            }
        }
        __syncthreads();
    }

    float inv0 = 1.f / lsum0, inv1 = 1.f / lsum1;
    size_t row0 = (size_t)(b * S_ + qb * 128 + wq0 + g);
    float* op0 = g_attn + row0 * D_ + h * 64;
    float* op1 = g_attn + (row0 + 8) * D_ + h * 64;
    #pragma unroll
    for (int nj = 0; nj < 8; nj++) {
        float2 w0; w0.x = o[nj][0] * inv0; w0.y = o[nj][1] * inv0;
        float2 w1; w1.x = o[nj][2] * inv1; w1.y = o[nj][3] * inv1;
        *(float2*)(op0 + nj * 8 + 2 * c) = w0;
        *(float2*)(op1 + nj * 8 + 2 * c) = w1;
    }
}

// ---------------- launch ----------------------------------------------------
extern "C" void kernel_launch(void* const* d_in, const int* in_sizes, int n_in,
                              void* d_out, int out_size) {
    const float* x    = (const float*)d_in[0];
    const int*   pm   = (const int*)  d_in[1];
    const float* wqkv = (const float*)d_in[2];
    const float* wo   = (const float*)d_in[3];
    float* out = (float*)d_out;

    cudaFuncSetAttribute(flash_bf16, cudaFuncAttributeMaxDynamicSharedMemorySize,
                         FB_SMEM_U32 * 4);

    rope_table_kernel<<<(S_ * 32 + 255) / 256, 256>>>();
    transpose_w<<<dim3(D_ / 32, NQKV / 32), dim3(32, 8)>>>(wqkv, NQKV, D_, 0);
    transpose_w<<<dim3(D_ / 32, D_  / 32), dim3(32, 8)>>>(wo,   D_,   D_, 1);

    mma_gemm3<NQKV, 0><<<dim3(NQKV / 128, M_ / 128), 256>>>(x, nullptr);
    flash_bf16<<<dim3(S_ / 128, H_, B_), 256, FB_SMEM_U32 * 4>>>(pm);
    mma_gemm3<D_, 1><<<dim3(D_ / 128, M_ / 128), 256>>>(nullptr, out);
}